// round 11
// baseline (speedup 1.0000x reference)
#include <cuda_runtime.h>
#include <cuda_fp16.h>
#include <cstdint>
#include <cstddef>

// Problem constants
#define BB 2
#define NN 4096
#define DD 512
#define HH 8
#define DH 64
#define SCALE_F 0.125f   // 64^-0.5
#define LOG2E_F 1.4426950408889634f

// Scratch (allocation-free rule: __device__ globals).
// NOTE: __device__ symbols must ONLY be referenced from device code.
__device__ __align__(16) __half g_xh[(size_t)BB * NN * DD];
__device__ __align__(16) __half g_xl[(size_t)BB * NN * DD];
__device__ __align__(16) __half g_wh[(size_t)4 * DD * DD];
__device__ __align__(16) __half g_wl[(size_t)4 * DD * DD];
__device__ __align__(16) __half g_qh [(size_t)BB * HH * NN * DH];
__device__ __align__(16) __half g_kh [(size_t)BB * HH * NN * DH];
__device__ __align__(16) __half g_vth[(size_t)BB * HH * NN * DH];
__device__ __align__(16) __half g_ah[(size_t)BB * NN * DD];
__device__ __align__(16) __half g_al[(size_t)BB * NN * DD];

// ===========================================================================
// Helpers (arch-neutral PTX only)
// ===========================================================================

__device__ __forceinline__ uint32_t smem_u32(const void* p) {
    uint32_t a;
    asm("{ .reg .u64 t; cvta.to.shared.u64 t, %1; cvt.u32.u64 %0, t; }"
        : "=r"(a) : "l"(p));
    return a;
}

__device__ __forceinline__ float ex2f(float x) {
    float y;
    asm("ex2.approx.ftz.f32 %0, %1;" : "=f"(y) : "f"(x));
    return y;
}

// D += A @ B, f32 accumulator
__device__ __forceinline__ void mma_f16(float* d, const uint32_t* a, const uint32_t* b) {
    asm volatile(
        "mma.sync.aligned.m16n8k16.row.col.f32.f16.f16.f32 "
        "{%0,%1,%2,%3}, {%4,%5,%6,%7}, {%8,%9}, {%0,%1,%2,%3};"
        : "+f"(d[0]), "+f"(d[1]), "+f"(d[2]), "+f"(d[3])
        : "r"(a[0]), "r"(a[1]), "r"(a[2]), "r"(a[3]), "r"(b[0]), "r"(b[1]));
}

// D += A @ B, f16 accumulator (D = 2x b32 = 4 halves)
__device__ __forceinline__ void mma_f16h(uint32_t* d, const uint32_t* a, const uint32_t* b) {
    asm volatile(
        "mma.sync.aligned.m16n8k16.row.col.f16.f16.f16.f16 "
        "{%0,%1}, {%2,%3,%4,%5}, {%6,%7}, {%0,%1};"
        : "+r"(d[0]), "+r"(d[1])
        : "r"(a[0]), "r"(a[1]), "r"(a[2]), "r"(a[3]), "r"(b[0]), "r"(b[1]));
}

__device__ __forceinline__ void cp_async16(uint32_t dst, const void* src) {
    asm volatile("cp.async.cg.shared.global [%0], [%1], 16;"
                 :: "r"(dst), "l"(src) : "memory");
}
#define CP_COMMIT() asm volatile("cp.async.commit_group;" ::: "memory")
#define CP_WAIT0()  asm volatile("cp.async.wait_group 0;" ::: "memory")

__device__ __forceinline__ uint32_t pack2(__half a, __half b) {
    __half2 h = __halves2half2(a, b);
    return *(uint32_t*)&h;
}

// split pair of floats into hi/lo fp16x2 words
__device__ __forceinline__ void split2(float a, float b, uint32_t& hi, uint32_t& lo) {
    __half ha = __float2half_rn(a), hb = __float2half_rn(b);
    hi = pack2(ha, hb);
    __half2 L = __floats2half2_rn(a - __half2float(ha), b - __half2float(hb));
    lo = *(uint32_t*)&L;
}

// P = exp2(d - m) in half2 domain, returns packed fp16x2 bits
__device__ __forceinline__ uint32_t p_h2(uint32_t d_bits, __half2 m2) {
    __half2 d = *(__half2*)&d_bits;
    __half2 p = h2exp2(__hsub2(d, m2));
    return *(uint32_t*)&p;
}

// XOR-swizzled LDS.32 from [row][64-half = 128B] tile
__device__ __forceinline__ uint32_t lds32(const char* base, uint32_t row, uint32_t chunk, uint32_t cB) {
    return *(const uint32_t*)(base + row * 128 + ((chunk ^ (row & 7u)) << 4) + cB * 4);
}

// ===========================================================================
// merged conversion kernel: fp32 -> (hi, lo) fp16 for x + all 4 weights.
// grid: [0,4096) = x ; [4096, 4096+4*256) = Wq,Wk,Wv,Wo
// ===========================================================================
__global__ __launch_bounds__(256) void conv_all_kernel(
    const float* __restrict__ x,
    const float* __restrict__ Wq, const float* __restrict__ Wk,
    const float* __restrict__ Wv, const float* __restrict__ Wo)
{
    const int bid = blockIdx.x;
    const float* src;
    __half *dh, *dl;
    int idx;
    if (bid < 4096) {
        src = x; dh = g_xh; dl = g_xl;
        idx = bid * 256 + threadIdx.x;
    } else {
        const int w = (bid - 4096) >> 8;      // 0..3
        src = (w == 0) ? Wq : (w == 1) ? Wk : (w == 2) ? Wv : Wo;
        const size_t off = (size_t)w * DD * DD;
        dh = g_wh + off; dl = g_wl + off;
        idx = ((bid - 4096) & 255) * 256 + threadIdx.x;
    }

    float4 f = ((const float4*)src)[idx];
    uint32_t h0, l0, h1, l1;
    split2(f.x, f.y, h0, l0);
    split2(f.z, f.w, h1, l1);
    uint32_t* dh32 = (uint32_t*)dh;
    uint32_t* dl32 = (uint32_t*)dl;
    dh32[idx * 2 + 0] = h0;
    dh32[idx * 2 + 1] = h1;
    dl32[idx * 2 + 0] = l0;
    dl32[idx * 2 + 1] = l1;
}

// ===========================================================================
// Split-fp16 GEMM: C ≈ Ah·Bh (f32 acc) + [Al·Bh + Ah·Bl] (f16 acc, folded at end)
// modes: z=0 Q, z=1 K, z=2 V^T (A/B roles swapped), z=3 out-proj.
// smem: 2 stages x 4 tiles x [128 rows][128B] = 128KB
// ===========================================================================

#define GEMM_SMEM 131072

__global__ __launch_bounds__(256) void hgemm_kernel(
    int mode_arg, const float* __restrict__ bo, float* __restrict__ outp)
{
    extern __shared__ char smem[];
    const uint32_t sbase = smem_u32(smem);

    const int tid  = threadIdx.x;
    const int lane = tid & 31;
    const int warp = tid >> 5;
    const int r0   = lane >> 2;
    const int cB   = lane & 3;
    const int wm   = (warp >> 1) * 32;
    const int wn   = (warp & 1) * 64;
    const int bx   = blockIdx.x;
    const int by   = blockIdx.y;
    const int z    = (mode_arg < 0) ? (int)blockIdx.z : mode_arg;

    const __half *pa_h, *pa_l, *pb_h, *pb_l;
    size_t arow0, brow0;
    if (z == 0)      { pa_h = g_xh; pa_l = g_xl; pb_h = g_wh;              pb_l = g_wl;              arow0 = (size_t)by * 128; brow0 = (size_t)bx * 128; }
    else if (z == 1) { pa_h = g_xh; pa_l = g_xl; pb_h = g_wh + 262144;     pb_l = g_wl + 262144;     arow0 = (size_t)by * 128; brow0 = (size_t)bx * 128; }
    else if (z == 2) { pa_h = g_wh + 2 * 262144; pa_l = g_wl + 2 * 262144; pb_h = g_xh; pb_l = g_xl; arow0 = (size_t)bx * 128; brow0 = (size_t)by * 128; }
    else             { pa_h = g_ah; pa_l = g_al; pb_h = g_wh + 3 * 262144; pb_l = g_wl + 3 * 262144; arow0 = (size_t)by * 128; brow0 = (size_t)bx * 128; }

    const int lrow = tid >> 1;
    const int c0l  = (tid & 1) * 4;

    auto issue = [&](int stage, int k0) {
        const uint32_t sw = ((uint32_t)lrow & 7u);
        const uint32_t rowoff = (uint32_t)lrow * 128u;
        const uint32_t st = sbase + stage * 65536;
        const __half* srcs[4] = {
            pa_h + (arow0 + lrow) * DD + k0,
            pa_l + (arow0 + lrow) * DD + k0,
            pb_h + (brow0 + lrow) * DD + k0,
            pb_l + (brow0 + lrow) * DD + k0 };
#pragma unroll
        for (int tile = 0; tile < 4; tile++) {
            const uint32_t tbase = st + tile * 16384 + rowoff;
#pragma unroll
            for (int i = 0; i < 4; i++) {
                const uint32_t c = (uint32_t)(c0l + i);
                cp_async16(tbase + ((c ^ sw) << 4), srcs[tile] + c * 8);
            }
        }
    };

    float acc[2][8][4];
    uint32_t corr[2][8][2];     // f16x2 accumulators for correction terms
#pragma unroll
    for (int mf = 0; mf < 2; mf++)
#pragma unroll
        for (int nf = 0; nf < 8; nf++) {
#pragma unroll
            for (int j = 0; j < 4; j++) acc[mf][nf][j] = 0.f;
            corr[mf][nf][0] = 0u; corr[mf][nf][1] = 0u;
        }

    issue(0, 0);
    CP_COMMIT();

    for (int kc = 0; kc < 8; kc++) {
        CP_WAIT0();
        __syncthreads();
        if (kc + 1 < 8) { issue((kc + 1) & 1, (kc + 1) * 64); CP_COMMIT(); }

        const char* sAh = smem + (kc & 1) * 65536;
        const char* sAl = sAh + 16384;
        const char* sBh = sAh + 32768;
        const char* sBl = sAh + 49152;

#pragma unroll
        for (int ks = 0; ks < 4; ks++) {
            uint32_t ah[2][4], al[2][4], wh[8][2], wl[8][2];
#pragma unroll
            for (int mf = 0; mf < 2; mf++) {
                const uint32_t ra = (uint32_t)(wm + mf * 16 + r0);
                ah[mf][0] = lds32(sAh, ra,     2 * ks,     cB);
                ah[mf][1] = lds32(sAh, ra + 8, 2 * ks,     cB);
                ah[mf][2] = lds32(sAh, ra,     2 * ks + 1, cB);
                ah[mf][3] = lds32(sAh, ra + 8, 2 * ks + 1, cB);
                al[mf][0] = lds32(sAl, ra,     2 * ks,     cB);
                al[mf][1] = lds32(sAl, ra + 8, 2 * ks,     cB);
                al[mf][2] = lds32(sAl, ra,     2 * ks + 1, cB);
                al[mf][3] = lds32(sAl, ra + 8, 2 * ks + 1, cB);
            }
#pragma unroll
            for (int nf = 0; nf < 8; nf++) {
                const uint32_t rb = (uint32_t)(wn + nf * 8 + r0);
                wh[nf][0] = lds32(sBh, rb, 2 * ks,     cB);
                wh[nf][1] = lds32(sBh, rb, 2 * ks + 1, cB);
                wl[nf][0] = lds32(sBl, rb, 2 * ks,     cB);
                wl[nf][1] = lds32(sBl, rb, 2 * ks + 1, cB);
            }
            // main term: f32 accumulator
#pragma unroll
            for (int mf = 0; mf < 2; mf++)
#pragma unroll
                for (int nf = 0; nf < 8; nf++)
                    mma_f16(acc[mf][nf], ah[mf], wh[nf]);
            // correction terms (~2^-11 of main): f16 accumulator
#pragma unroll
            for (int mf = 0; mf < 2; mf++)
#pragma unroll
                for (int nf = 0; nf < 8; nf++)
                    mma_f16h(corr[mf][nf], al[mf], wh[nf]);
#pragma unroll
            for (int mf = 0; mf < 2; mf++)
#pragma unroll
                for (int nf = 0; nf < 8; nf++)
                    mma_f16h(corr[mf][nf], ah[mf], wl[nf]);
        }
    }

    // fold corrections into f32 accumulators
#pragma unroll
    for (int mf = 0; mf < 2; mf++)
#pragma unroll
        for (int nf = 0; nf < 8; nf++) {
            float2 c01 = __half22float2(*(__half2*)&corr[mf][nf][0]);
            float2 c23 = __half22float2(*(__half2*)&corr[mf][nf][1]);
            acc[mf][nf][0] += c01.x; acc[mf][nf][1] += c01.y;
            acc[mf][nf][2] += c23.x; acc[mf][nf][3] += c23.y;
        }

    if (z == 0 || z == 1) {
        __half* outq = (z == 0) ? g_qh : g_kh;
        const float sc = (z == 0) ? (SCALE_F * LOG2E_F) : 1.f;
#pragma unroll
        for (int mf = 0; mf < 2; mf++) {
            const int tokA = by * 128 + wm + mf * 16 + r0;
#pragma unroll
            for (int nf = 0; nf < 8; nf++) {
                const int oo = bx * 128 + wn + nf * 8 + 2 * cB;
                const int h = oo >> 6, dd = oo & 63;
#pragma unroll
                for (int half_ = 0; half_ < 2; half_++) {
                    const int tok = tokA + half_ * 8;
                    const int b = tok >> 12, n = tok & (NN - 1);
                    const float v0 = acc[mf][nf][2 * half_ + 0] * sc;
                    const float v1 = acc[mf][nf][2 * half_ + 1] * sc;
                    *(uint32_t*)(outq + (((size_t)(b * HH + h) * NN) + n) * DH + dd) =
                        pack2(__float2half_rn(v0), __float2half_rn(v1));
                }
            }
        }
    } else if (z == 2) {
#pragma unroll
        for (int mf = 0; mf < 2; mf++) {
            const int frA = bx * 128 + wm + mf * 16 + r0;
#pragma unroll
            for (int nf = 0; nf < 8; nf++) {
                const int tk = by * 128 + wn + nf * 8 + 2 * cB;
                const int b = tk >> 12, n = tk & (NN - 1);
#pragma unroll
                for (int half_ = 0; half_ < 2; half_++) {
                    const int fr = frA + half_ * 8;
                    const int h = fr >> 6, dd = fr & 63;
                    const float v0 = acc[mf][nf][2 * half_ + 0];
                    const float v1 = acc[mf][nf][2 * half_ + 1];
                    *(uint32_t*)(g_vth + (((size_t)(b * HH + h) * DH) + dd) * NN + n) =
                        pack2(__float2half_rn(v0), __float2half_rn(v1));
                }
            }
        }
    } else {
#pragma unroll
        for (int mf = 0; mf < 2; mf++) {
            const int tokA = by * 128 + wm + mf * 16 + r0;
#pragma unroll
            for (int nf = 0; nf < 8; nf++) {
                const int oo = bx * 128 + wn + nf * 8 + 2 * cB;
                const float b0 = bo[oo], b1 = bo[oo + 1];
#pragma unroll
                for (int half_ = 0; half_ < 2; half_++) {
                    const int tok = tokA + half_ * 8;
                    float2 v;
                    v.x = acc[mf][nf][2 * half_ + 0] + b0;
                    v.y = acc[mf][nf][2 * half_ + 1] + b1;
                    *(float2*)(outp + (size_t)tok * DD + oo) = v;
                }
            }
        }
    }
}

// ===========================================================================
// Flash attention: QK f16-acc, half2 softmax, l via ALU (no lsum mma),
// PV f32-acc. Guarded rescale.
// ===========================================================================

#define SM_TOT 32768

__global__ void __launch_bounds__(256, 2) attn_mma_kernel()
{
    extern __shared__ char smem[];
    const uint32_t sbase = smem_u32(smem);

    const int tid  = threadIdx.x;
    const int lane = tid & 31;
    const int warp = tid >> 5;
    const int bh   = blockIdx.y;
    const int q0   = blockIdx.x * 128;
    const int wrow = warp * 16;
    const int r0   = lane >> 2;
    const int cB   = lane & 3;

    const __half* khg  = g_kh  + (size_t)bh * NN * DH;
    const __half* vthg = g_vth + (size_t)bh * NN * DH;

    const int rowL = tid >> 2;
    const int fq   = tid & 3;

    {
        const char* ksrc = (const char*)(khg + (size_t)rowL * DH);
        const char* vsrc = (const char*)(vthg + (size_t)rowL * NN);
        const uint32_t kdst = sbase + rowL * 128;
        const uint32_t vdst = sbase + 16384 + rowL * 128;
        const uint32_t sw = (uint32_t)(rowL & 7);
        cp_async16(kdst + (((uint32_t)fq       ^ sw) << 4), ksrc + fq * 16);
        cp_async16(kdst + (((uint32_t)(fq + 4) ^ sw) << 4), ksrc + (fq + 4) * 16);
        cp_async16(vdst + (((uint32_t)fq       ^ sw) << 4), vsrc + fq * 16);
        cp_async16(vdst + (((uint32_t)(fq + 4) ^ sw) << 4), vsrc + (fq + 4) * 16);
        CP_COMMIT();
    }

    uint32_t qa[4][4];
    {
        const __half* qg = g_qh + ((size_t)bh * NN + q0 + wrow + r0) * DH;
#pragma unroll
        for (int s4 = 0; s4 < 4; s4++) {
            qa[s4][0] = *(const uint32_t*)(qg + s4 * 16 + 2 * cB);
            qa[s4][1] = *(const uint32_t*)(qg + 8 * DH + s4 * 16 + 2 * cB);
            qa[s4][2] = *(const uint32_t*)(qg + s4 * 16 + 2 * cB + 8);
            qa[s4][3] = *(const uint32_t*)(qg + 8 * DH + s4 * 16 + 2 * cB + 8);
        }
    }

    float o[8][4];
#pragma unroll
    for (int n = 0; n < 8; n++)
#pragma unroll
        for (int j = 0; j < 4; j++) o[n][j] = 0.f;
    float m0 = -1e30f, m1 = -1e30f, l0 = 0.f, l1 = 0.f;

    for (int t = 0; t < NN / 64; t++) {
        CP_WAIT0();
        __syncthreads();

        if (t + 1 < NN / 64) {
            const int buf = (t + 1) & 1;
            const char* ksrc = (const char*)(khg + ((size_t)(t + 1) * 64 + rowL) * DH);
            const char* vsrc = (const char*)(vthg + (size_t)rowL * NN + (t + 1) * 64);
            const uint32_t kdst = sbase + buf * 8192 + rowL * 128;
            const uint32_t vdst = sbase + 16384 + buf * 8192 + rowL * 128;
            const uint32_t sw = (uint32_t)(rowL & 7);
            cp_async16(kdst + (((uint32_t)fq       ^ sw) << 4), ksrc + fq * 16);
            cp_async16(kdst + (((uint32_t)(fq + 4) ^ sw) << 4), ksrc + (fq + 4) * 16);
            cp_async16(vdst + (((uint32_t)fq       ^ sw) << 4), vsrc + fq * 16);
            cp_async16(vdst + (((uint32_t)(fq + 4) ^ sw) << 4), vsrc + (fq + 4) * 16);
            CP_COMMIT();
        }

        const char* sK = smem + (t & 1) * 8192;
        const char* sV = smem + 16384 + (t & 1) * 8192;

        // ---- S = Q @ K^T, f16 accumulator ----
        uint32_t sc[8][2];
#pragma unroll
        for (int n = 0; n < 8; n++) { sc[n][0] = 0u; sc[n][1] = 0u; }

#pragma unroll
        for (int s4 = 0; s4 < 4; s4++) {
#pragma unroll
            for (int n = 0; n < 8; n++) {
                const uint32_t row = (uint32_t)(n * 8 + r0);
                uint32_t b[2];
                b[0] = lds32(sK, row, 2 * s4,     (uint32_t)cB);
                b[1] = lds32(sK, row, 2 * s4 + 1, (uint32_t)cB);
                mma_f16h(sc[n], qa[s4], b);
            }
        }

        // ---- online softmax, half2 domain ----
        __half2 hx0 = *(__half2*)&sc[0][0];
        __half2 hx1 = *(__half2*)&sc[0][1];
#pragma unroll
        for (int n = 1; n < 8; n++) {
            hx0 = __hmax2(hx0, *(__half2*)&sc[n][0]);
            hx1 = __hmax2(hx1, *(__half2*)&sc[n][1]);
        }
        float mx0 = fmaxf(__low2float(hx0), __high2float(hx0));
        float mx1 = fmaxf(__low2float(hx1), __high2float(hx1));
        mx0 = fmaxf(mx0, __shfl_xor_sync(0xffffffffu, mx0, 1));
        mx0 = fmaxf(mx0, __shfl_xor_sync(0xffffffffu, mx0, 2));
        mx1 = fmaxf(mx1, __shfl_xor_sync(0xffffffffu, mx1, 1));
        mx1 = fmaxf(mx1, __shfl_xor_sync(0xffffffffu, mx1, 2));

        if (mx0 > m0) {
            const float a0 = ex2f(m0 - mx0);
            l0 *= a0;
#pragma unroll
            for (int n = 0; n < 8; n++) { o[n][0] *= a0; o[n][1] *= a0; }
            m0 = mx0;
        }
        if (mx1 > m1) {
            const float a1 = ex2f(m1 - mx1);
            l1 *= a1;
#pragma unroll
            for (int n = 0; n < 8; n++) { o[n][2] *= a1; o[n][3] *= a1; }
            m1 = mx1;
        }

        const __half2 m0h2 = __floats2half2_rn(m0, m0);
        const __half2 m1h2 = __floats2half2_rn(m1, m1);

        // ---- P = exp2(S - m); O += P @ V; l via ALU partial + quad reduce ----
        float lt0 = 0.f, lt1 = 0.f;
#pragma unroll
        for (int s4 = 0; s4 < 4; s4++) {
            uint32_t pa[4];
            pa[0] = p_h2(sc[2 * s4][0],     m0h2);
            pa[1] = p_h2(sc[2 * s4][1],     m1h2);
            pa[2] = p_h2(sc[2 * s4 + 1][0], m0h2);
            pa[3] = p_h2(sc[2 * s4 + 1][1], m1h2);

            __half2 ps0 = __hadd2(*(__half2*)&pa[0], *(__half2*)&pa[2]);
            __half2 ps1 = __hadd2(*(__half2*)&pa[1], *(__half2*)&pa[3]);
            float2 f0 = __half22float2(ps0);
            float2 f1 = __half22float2(ps1);
            lt0 += f0.x + f0.y;
            lt1 += f1.x + f1.y;

#pragma unroll
            for (int n = 0; n < 8; n++) {
                const uint32_t row = (uint32_t)(n * 8 + r0);
                uint32_t b[2];
                b[0] = lds32(sV, row, 2 * s4,     (uint32_t)cB);
                b[1] = lds32(sV, row, 2 * s4 + 1, (uint32_t)cB);
                mma_f16(o[n], pa, b);
            }
        }
        lt0 += __shfl_xor_sync(0xffffffffu, lt0, 1);
        lt0 += __shfl_xor_sync(0xffffffffu, lt0, 2);
        lt1 += __shfl_xor_sync(0xffffffffu, lt1, 1);
        lt1 += __shfl_xor_sync(0xffffffffu, lt1, 2);
        l0 += lt0;
        l1 += lt1;
    }

    // ---- epilogue: normalize, split to hi/lo fp16 for out-proj ----
    const float inv0 = 1.f / l0;
    const float inv1 = 1.f / l1;
    const int b = bh >> 3, h = bh & 7;
    const int row0 = q0 + wrow + r0;
    const size_t off0 = ((size_t)(b * NN + row0)) * DD + h * DH;
    const size_t off1 = off0 + (size_t)8 * DD;
#pragma unroll
    for (int n = 0; n < 8; n++) {
        const int col = n * 8 + 2 * cB;
        uint32_t h0, lo0, h1, lo1;
        split2(o[n][0] * inv0, o[n][1] * inv0, h0, lo0);
        split2(o[n][2] * inv1, o[n][3] * inv1, h1, lo1);
        *(uint32_t*)(g_ah + off0 + col) = h0;
        *(uint32_t*)(g_al + off0 + col) = lo0;
        *(uint32_t*)(g_ah + off1 + col) = h1;
        *(uint32_t*)(g_al + off1 + col) = lo1;
    }
}

// ===========================================================================

extern "C" void kernel_launch(void* const* d_in, const int* in_sizes, int n_in,
                              void* d_out, int out_size)
{
    (void)in_sizes; (void)n_in; (void)out_size;
    const float* x  = (const float*)d_in[0];
    const float* Wq = (const float*)d_in[1];
    const float* Wk = (const float*)d_in[2];
    const float* Wv = (const float*)d_in[3];
    const float* Wo = (const float*)d_in[4];
    const float* bo = (const float*)d_in[5];
    float* out = (float*)d_out;

    cudaFuncSetAttribute(hgemm_kernel,
                         cudaFuncAttributeMaxDynamicSharedMemorySize, GEMM_SMEM);
    cudaFuncSetAttribute(attn_mma_kernel,
                         cudaFuncAttributeMaxDynamicSharedMemorySize, SM_TOT);

    // merged split conversions (x + 4 weights) in one launch
    conv_all_kernel<<<4096 + 4 * 256, 256>>>(x, Wq, Wk, Wv, Wo);

    // QKV projections (tensor cores, split-fp16)
    hgemm_kernel<<<dim3(4, 64, 3), 256, GEMM_SMEM>>>(-1, nullptr, nullptr);
    // Flash attention
    attn_mma_kernel<<<dim3(NN / 128, BB * HH), 256, SM_TOT>>>();
    // Output projection + bias
    hgemm_kernel<<<dim3(4, 64, 1), 256, GEMM_SMEM>>>(3, bo, out);
}

// round 12
// speedup vs baseline: 1.5848x; 1.5848x over previous
#include <cuda_runtime.h>
#include <cuda_fp16.h>
#include <cstdint>
#include <cstddef>

// Problem constants
#define BB 2
#define NN 4096
#define DD 512
#define HH 8
#define DH 64
#define SCALE_F 0.125f   // 64^-0.5
#define LOG2E_F 1.4426950408889634f

// Scratch (allocation-free rule: __device__ globals).
// NOTE: __device__ symbols must ONLY be referenced from device code.
__device__ __align__(16) __half g_xh[(size_t)BB * NN * DD];
__device__ __align__(16) __half g_xl[(size_t)BB * NN * DD];
__device__ __align__(16) __half g_wh[(size_t)4 * DD * DD];
__device__ __align__(16) __half g_wl[(size_t)4 * DD * DD];
__device__ __align__(16) __half g_qh [(size_t)BB * HH * NN * DH];
__device__ __align__(16) __half g_kh [(size_t)BB * HH * NN * DH];
__device__ __align__(16) __half g_vth[(size_t)BB * HH * NN * DH];
__device__ __align__(16) __half g_ah[(size_t)BB * NN * DD];
__device__ __align__(16) __half g_al[(size_t)BB * NN * DD];

// ===========================================================================
// Helpers (arch-neutral PTX only)
// ===========================================================================

__device__ __forceinline__ uint32_t smem_u32(const void* p) {
    uint32_t a;
    asm("{ .reg .u64 t; cvta.to.shared.u64 t, %1; cvt.u32.u64 %0, t; }"
        : "=r"(a) : "l"(p));
    return a;
}

__device__ __forceinline__ float ex2f(float x) {
    float y;
    asm("ex2.approx.ftz.f32 %0, %1;" : "=f"(y) : "f"(x));
    return y;
}

// D += A @ B, f32 accumulator
__device__ __forceinline__ void mma_f16(float* d, const uint32_t* a, const uint32_t* b) {
    asm volatile(
        "mma.sync.aligned.m16n8k16.row.col.f32.f16.f16.f32 "
        "{%0,%1,%2,%3}, {%4,%5,%6,%7}, {%8,%9}, {%0,%1,%2,%3};"
        : "+f"(d[0]), "+f"(d[1]), "+f"(d[2]), "+f"(d[3])
        : "r"(a[0]), "r"(a[1]), "r"(a[2]), "r"(a[3]), "r"(b[0]), "r"(b[1]));
}

// D += A @ B, f16 accumulator (D = 2x b32 = 4 halves)
__device__ __forceinline__ void mma_f16h(uint32_t* d, const uint32_t* a, const uint32_t* b) {
    asm volatile(
        "mma.sync.aligned.m16n8k16.row.col.f16.f16.f16.f16 "
        "{%0,%1}, {%2,%3,%4,%5}, {%6,%7}, {%0,%1};"
        : "+r"(d[0]), "+r"(d[1])
        : "r"(a[0]), "r"(a[1]), "r"(a[2]), "r"(a[3]), "r"(b[0]), "r"(b[1]));
}

__device__ __forceinline__ void cp_async16(uint32_t dst, const void* src) {
    asm volatile("cp.async.cg.shared.global [%0], [%1], 16;"
                 :: "r"(dst), "l"(src) : "memory");
}
#define CP_COMMIT() asm volatile("cp.async.commit_group;" ::: "memory")
#define CP_WAIT0()  asm volatile("cp.async.wait_group 0;" ::: "memory")

__device__ __forceinline__ uint32_t pack2(__half a, __half b) {
    __half2 h = __halves2half2(a, b);
    return *(uint32_t*)&h;
}

// split pair of floats into hi/lo fp16x2 words
__device__ __forceinline__ void split2(float a, float b, uint32_t& hi, uint32_t& lo) {
    __half ha = __float2half_rn(a), hb = __float2half_rn(b);
    hi = pack2(ha, hb);
    __half2 L = __floats2half2_rn(a - __half2float(ha), b - __half2float(hb));
    lo = *(uint32_t*)&L;
}

// P = exp2(d - m) in half2 domain, returns packed fp16x2 bits
__device__ __forceinline__ uint32_t p_h2(uint32_t d_bits, __half2 m2) {
    __half2 d = *(__half2*)&d_bits;
    __half2 p = h2exp2(__hsub2(d, m2));
    return *(uint32_t*)&p;
}

// XOR-swizzled LDS.32 from [row][64-half = 128B] tile
__device__ __forceinline__ uint32_t lds32(const char* base, uint32_t row, uint32_t chunk, uint32_t cB) {
    return *(const uint32_t*)(base + row * 128 + ((chunk ^ (row & 7u)) << 4) + cB * 4);
}

// ===========================================================================
// merged conversion kernel: fp32 -> (hi, lo) fp16 for x + all 4 weights.
// grid: [0,4096) = x ; [4096, 4096+4*256) = Wq,Wk,Wv,Wo
// ===========================================================================
__global__ __launch_bounds__(256) void conv_all_kernel(
    const float* __restrict__ x,
    const float* __restrict__ Wq, const float* __restrict__ Wk,
    const float* __restrict__ Wv, const float* __restrict__ Wo)
{
    const int bid = blockIdx.x;
    const float* src;
    __half *dh, *dl;
    int idx;
    if (bid < 4096) {
        src = x; dh = g_xh; dl = g_xl;
        idx = bid * 256 + threadIdx.x;
    } else {
        const int w = (bid - 4096) >> 8;      // 0..3
        src = (w == 0) ? Wq : (w == 1) ? Wk : (w == 2) ? Wv : Wo;
        const size_t off = (size_t)w * DD * DD;
        dh = g_wh + off; dl = g_wl + off;
        idx = ((bid - 4096) & 255) * 256 + threadIdx.x;
    }

    float4 f = ((const float4*)src)[idx];
    uint32_t h0, l0, h1, l1;
    split2(f.x, f.y, h0, l0);
    split2(f.z, f.w, h1, l1);
    uint32_t* dh32 = (uint32_t*)dh;
    uint32_t* dl32 = (uint32_t*)dl;
    dh32[idx * 2 + 0] = h0;
    dh32[idx * 2 + 1] = h1;
    dl32[idx * 2 + 0] = l0;
    dl32[idx * 2 + 1] = l1;
}

// ===========================================================================
// Split-fp16 GEMM (R10-proven): C ≈ Ah·Bh + Al·Bh + Ah·Bl, all f32-acc mma.
// modes: z=0 Q, z=1 K, z=2 V^T (A/B roles swapped), z=3 out-proj.
// smem: 2 stages x 4 tiles x [128 rows][128B] = 128KB
// ===========================================================================

#define GEMM_SMEM 131072

__global__ __launch_bounds__(256) void hgemm_kernel(
    int mode_arg, const float* __restrict__ bo, float* __restrict__ outp)
{
    extern __shared__ char smem[];
    const uint32_t sbase = smem_u32(smem);

    const int tid  = threadIdx.x;
    const int lane = tid & 31;
    const int warp = tid >> 5;
    const int r0   = lane >> 2;
    const int cB   = lane & 3;
    const int wm   = (warp >> 1) * 32;
    const int wn   = (warp & 1) * 64;
    const int bx   = blockIdx.x;
    const int by   = blockIdx.y;
    const int z    = (mode_arg < 0) ? (int)blockIdx.z : mode_arg;

    const __half *pa_h, *pa_l, *pb_h, *pb_l;
    size_t arow0, brow0;
    if (z == 0)      { pa_h = g_xh; pa_l = g_xl; pb_h = g_wh;              pb_l = g_wl;              arow0 = (size_t)by * 128; brow0 = (size_t)bx * 128; }
    else if (z == 1) { pa_h = g_xh; pa_l = g_xl; pb_h = g_wh + 262144;     pb_l = g_wl + 262144;     arow0 = (size_t)by * 128; brow0 = (size_t)bx * 128; }
    else if (z == 2) { pa_h = g_wh + 2 * 262144; pa_l = g_wl + 2 * 262144; pb_h = g_xh; pb_l = g_xl; arow0 = (size_t)bx * 128; brow0 = (size_t)by * 128; }
    else             { pa_h = g_ah; pa_l = g_al; pb_h = g_wh + 3 * 262144; pb_l = g_wl + 3 * 262144; arow0 = (size_t)by * 128; brow0 = (size_t)bx * 128; }

    const int lrow = tid >> 1;
    const int c0l  = (tid & 1) * 4;

    auto issue = [&](int stage, int k0) {
        const uint32_t sw = ((uint32_t)lrow & 7u);
        const uint32_t rowoff = (uint32_t)lrow * 128u;
        const uint32_t st = sbase + stage * 65536;
        const __half* srcs[4] = {
            pa_h + (arow0 + lrow) * DD + k0,
            pa_l + (arow0 + lrow) * DD + k0,
            pb_h + (brow0 + lrow) * DD + k0,
            pb_l + (brow0 + lrow) * DD + k0 };
#pragma unroll
        for (int tile = 0; tile < 4; tile++) {
            const uint32_t tbase = st + tile * 16384 + rowoff;
#pragma unroll
            for (int i = 0; i < 4; i++) {
                const uint32_t c = (uint32_t)(c0l + i);
                cp_async16(tbase + ((c ^ sw) << 4), srcs[tile] + c * 8);
            }
        }
    };

    float acc[2][8][4];
#pragma unroll
    for (int mf = 0; mf < 2; mf++)
#pragma unroll
        for (int nf = 0; nf < 8; nf++)
#pragma unroll
            for (int j = 0; j < 4; j++) acc[mf][nf][j] = 0.f;

    issue(0, 0);
    CP_COMMIT();

    for (int kc = 0; kc < 8; kc++) {
        CP_WAIT0();
        __syncthreads();
        if (kc + 1 < 8) { issue((kc + 1) & 1, (kc + 1) * 64); CP_COMMIT(); }

        const char* sAh = smem + (kc & 1) * 65536;
        const char* sAl = sAh + 16384;
        const char* sBh = sAh + 32768;
        const char* sBl = sAh + 49152;

#pragma unroll
        for (int ks = 0; ks < 4; ks++) {
            uint32_t ah[2][4], al[2][4], wh[8][2], wl[8][2];
#pragma unroll
            for (int mf = 0; mf < 2; mf++) {
                const uint32_t ra = (uint32_t)(wm + mf * 16 + r0);
                ah[mf][0] = lds32(sAh, ra,     2 * ks,     cB);
                ah[mf][1] = lds32(sAh, ra + 8, 2 * ks,     cB);
                ah[mf][2] = lds32(sAh, ra,     2 * ks + 1, cB);
                ah[mf][3] = lds32(sAh, ra + 8, 2 * ks + 1, cB);
                al[mf][0] = lds32(sAl, ra,     2 * ks,     cB);
                al[mf][1] = lds32(sAl, ra + 8, 2 * ks,     cB);
                al[mf][2] = lds32(sAl, ra,     2 * ks + 1, cB);
                al[mf][3] = lds32(sAl, ra + 8, 2 * ks + 1, cB);
            }
#pragma unroll
            for (int nf = 0; nf < 8; nf++) {
                const uint32_t rb = (uint32_t)(wn + nf * 8 + r0);
                wh[nf][0] = lds32(sBh, rb, 2 * ks,     cB);
                wh[nf][1] = lds32(sBh, rb, 2 * ks + 1, cB);
                wl[nf][0] = lds32(sBl, rb, 2 * ks,     cB);
                wl[nf][1] = lds32(sBl, rb, 2 * ks + 1, cB);
            }
#pragma unroll
            for (int mf = 0; mf < 2; mf++)
#pragma unroll
                for (int nf = 0; nf < 8; nf++)
                    mma_f16(acc[mf][nf], ah[mf], wh[nf]);
#pragma unroll
            for (int mf = 0; mf < 2; mf++)
#pragma unroll
                for (int nf = 0; nf < 8; nf++)
                    mma_f16(acc[mf][nf], al[mf], wh[nf]);
#pragma unroll
            for (int mf = 0; mf < 2; mf++)
#pragma unroll
                for (int nf = 0; nf < 8; nf++)
                    mma_f16(acc[mf][nf], ah[mf], wl[nf]);
        }
    }

    if (z == 0 || z == 1) {
        __half* outq = (z == 0) ? g_qh : g_kh;
        const float sc = (z == 0) ? (SCALE_F * LOG2E_F) : 1.f;
#pragma unroll
        for (int mf = 0; mf < 2; mf++) {
            const int tokA = by * 128 + wm + mf * 16 + r0;
#pragma unroll
            for (int nf = 0; nf < 8; nf++) {
                const int oo = bx * 128 + wn + nf * 8 + 2 * cB;
                const int h = oo >> 6, dd = oo & 63;
#pragma unroll
                for (int half_ = 0; half_ < 2; half_++) {
                    const int tok = tokA + half_ * 8;
                    const int b = tok >> 12, n = tok & (NN - 1);
                    const float v0 = acc[mf][nf][2 * half_ + 0] * sc;
                    const float v1 = acc[mf][nf][2 * half_ + 1] * sc;
                    *(uint32_t*)(outq + (((size_t)(b * HH + h) * NN) + n) * DH + dd) =
                        pack2(__float2half_rn(v0), __float2half_rn(v1));
                }
            }
        }
    } else if (z == 2) {
#pragma unroll
        for (int mf = 0; mf < 2; mf++) {
            const int frA = bx * 128 + wm + mf * 16 + r0;
#pragma unroll
            for (int nf = 0; nf < 8; nf++) {
                const int tk = by * 128 + wn + nf * 8 + 2 * cB;
                const int b = tk >> 12, n = tk & (NN - 1);
#pragma unroll
                for (int half_ = 0; half_ < 2; half_++) {
                    const int fr = frA + half_ * 8;
                    const int h = fr >> 6, dd = fr & 63;
                    const float v0 = acc[mf][nf][2 * half_ + 0];
                    const float v1 = acc[mf][nf][2 * half_ + 1];
                    *(uint32_t*)(g_vth + (((size_t)(b * HH + h) * DH) + dd) * NN + n) =
                        pack2(__float2half_rn(v0), __float2half_rn(v1));
                }
            }
        }
    } else {
#pragma unroll
        for (int mf = 0; mf < 2; mf++) {
            const int tokA = by * 128 + wm + mf * 16 + r0;
#pragma unroll
            for (int nf = 0; nf < 8; nf++) {
                const int oo = bx * 128 + wn + nf * 8 + 2 * cB;
                const float b0 = bo[oo], b1 = bo[oo + 1];
#pragma unroll
                for (int half_ = 0; half_ < 2; half_++) {
                    const int tok = tokA + half_ * 8;
                    float2 v;
                    v.x = acc[mf][nf][2 * half_ + 0] + b0;
                    v.y = acc[mf][nf][2 * half_ + 1] + b1;
                    *(float2*)(outp + (size_t)tok * DD + oo) = v;
                }
            }
        }
    }
}

// ===========================================================================
// Flash attention (R10-proven): QK f16-acc, half2 softmax, guarded rescale,
// l via ones-mma, PV f32-acc.
// ===========================================================================

#define SM_TOT 32768

__global__ void __launch_bounds__(256, 2) attn_mma_kernel()
{
    extern __shared__ char smem[];
    const uint32_t sbase = smem_u32(smem);

    const int tid  = threadIdx.x;
    const int lane = tid & 31;
    const int warp = tid >> 5;
    const int bh   = blockIdx.y;
    const int q0   = blockIdx.x * 128;
    const int wrow = warp * 16;
    const int r0   = lane >> 2;
    const int cB   = lane & 3;

    const __half* khg  = g_kh  + (size_t)bh * NN * DH;
    const __half* vthg = g_vth + (size_t)bh * NN * DH;

    const int rowL = tid >> 2;
    const int fq   = tid & 3;

    {
        const char* ksrc = (const char*)(khg + (size_t)rowL * DH);
        const char* vsrc = (const char*)(vthg + (size_t)rowL * NN);
        const uint32_t kdst = sbase + rowL * 128;
        const uint32_t vdst = sbase + 16384 + rowL * 128;
        const uint32_t sw = (uint32_t)(rowL & 7);
        cp_async16(kdst + (((uint32_t)fq       ^ sw) << 4), ksrc + fq * 16);
        cp_async16(kdst + (((uint32_t)(fq + 4) ^ sw) << 4), ksrc + (fq + 4) * 16);
        cp_async16(vdst + (((uint32_t)fq       ^ sw) << 4), vsrc + fq * 16);
        cp_async16(vdst + (((uint32_t)(fq + 4) ^ sw) << 4), vsrc + (fq + 4) * 16);
        CP_COMMIT();
    }

    uint32_t qa[4][4];
    {
        const __half* qg = g_qh + ((size_t)bh * NN + q0 + wrow + r0) * DH;
#pragma unroll
        for (int s4 = 0; s4 < 4; s4++) {
            qa[s4][0] = *(const uint32_t*)(qg + s4 * 16 + 2 * cB);
            qa[s4][1] = *(const uint32_t*)(qg + 8 * DH + s4 * 16 + 2 * cB);
            qa[s4][2] = *(const uint32_t*)(qg + s4 * 16 + 2 * cB + 8);
            qa[s4][3] = *(const uint32_t*)(qg + 8 * DH + s4 * 16 + 2 * cB + 8);
        }
    }

    float o[8][4];
#pragma unroll
    for (int n = 0; n < 8; n++)
#pragma unroll
        for (int j = 0; j < 4; j++) o[n][j] = 0.f;
    float m0 = -1e30f, m1 = -1e30f, l0 = 0.f, l1 = 0.f;

    const uint32_t ones[2] = {0x3C003C00u, 0x3C003C00u};

    for (int t = 0; t < NN / 64; t++) {
        CP_WAIT0();
        __syncthreads();

        if (t + 1 < NN / 64) {
            const int buf = (t + 1) & 1;
            const char* ksrc = (const char*)(khg + ((size_t)(t + 1) * 64 + rowL) * DH);
            const char* vsrc = (const char*)(vthg + (size_t)rowL * NN + (t + 1) * 64);
            const uint32_t kdst = sbase + buf * 8192 + rowL * 128;
            const uint32_t vdst = sbase + 16384 + buf * 8192 + rowL * 128;
            const uint32_t sw = (uint32_t)(rowL & 7);
            cp_async16(kdst + (((uint32_t)fq       ^ sw) << 4), ksrc + fq * 16);
            cp_async16(kdst + (((uint32_t)(fq + 4) ^ sw) << 4), ksrc + (fq + 4) * 16);
            cp_async16(vdst + (((uint32_t)fq       ^ sw) << 4), vsrc + fq * 16);
            cp_async16(vdst + (((uint32_t)(fq + 4) ^ sw) << 4), vsrc + (fq + 4) * 16);
            CP_COMMIT();
        }

        const char* sK = smem + (t & 1) * 8192;
        const char* sV = smem + 16384 + (t & 1) * 8192;

        // ---- S = Q @ K^T, f16 accumulator ----
        uint32_t sc[8][2];
#pragma unroll
        for (int n = 0; n < 8; n++) { sc[n][0] = 0u; sc[n][1] = 0u; }

#pragma unroll
        for (int s4 = 0; s4 < 4; s4++) {
#pragma unroll
            for (int n = 0; n < 8; n++) {
                const uint32_t row = (uint32_t)(n * 8 + r0);
                uint32_t b[2];
                b[0] = lds32(sK, row, 2 * s4,     (uint32_t)cB);
                b[1] = lds32(sK, row, 2 * s4 + 1, (uint32_t)cB);
                mma_f16h(sc[n], qa[s4], b);
            }
        }

        // ---- online softmax, half2 domain ----
        __half2 hx0 = *(__half2*)&sc[0][0];
        __half2 hx1 = *(__half2*)&sc[0][1];
#pragma unroll
        for (int n = 1; n < 8; n++) {
            hx0 = __hmax2(hx0, *(__half2*)&sc[n][0]);
            hx1 = __hmax2(hx1, *(__half2*)&sc[n][1]);
        }
        float mx0 = fmaxf(__low2float(hx0), __high2float(hx0));
        float mx1 = fmaxf(__low2float(hx1), __high2float(hx1));
        mx0 = fmaxf(mx0, __shfl_xor_sync(0xffffffffu, mx0, 1));
        mx0 = fmaxf(mx0, __shfl_xor_sync(0xffffffffu, mx0, 2));
        mx1 = fmaxf(mx1, __shfl_xor_sync(0xffffffffu, mx1, 1));
        mx1 = fmaxf(mx1, __shfl_xor_sync(0xffffffffu, mx1, 2));

        if (mx0 > m0) {
            const float a0 = ex2f(m0 - mx0);
            l0 *= a0;
#pragma unroll
            for (int n = 0; n < 8; n++) { o[n][0] *= a0; o[n][1] *= a0; }
            m0 = mx0;
        }
        if (mx1 > m1) {
            const float a1 = ex2f(m1 - mx1);
            l1 *= a1;
#pragma unroll
            for (int n = 0; n < 8; n++) { o[n][2] *= a1; o[n][3] *= a1; }
            m1 = mx1;
        }

        const __half2 m0h2 = __floats2half2_rn(m0, m0);
        const __half2 m1h2 = __floats2half2_rn(m1, m1);

        // ---- P = exp2(S - m); O += P @ V; l via ones-mma ----
        float ls[4] = {0.f, 0.f, 0.f, 0.f};
#pragma unroll
        for (int s4 = 0; s4 < 4; s4++) {
            uint32_t pa[4];
            pa[0] = p_h2(sc[2 * s4][0],     m0h2);
            pa[1] = p_h2(sc[2 * s4][1],     m1h2);
            pa[2] = p_h2(sc[2 * s4 + 1][0], m0h2);
            pa[3] = p_h2(sc[2 * s4 + 1][1], m1h2);
            mma_f16(ls, pa, ones);
#pragma unroll
            for (int n = 0; n < 8; n++) {
                const uint32_t row = (uint32_t)(n * 8 + r0);
                uint32_t b[2];
                b[0] = lds32(sV, row, 2 * s4,     (uint32_t)cB);
                b[1] = lds32(sV, row, 2 * s4 + 1, (uint32_t)cB);
                mma_f16(o[n], pa, b);
            }
        }
        l0 += ls[0];
        l1 += ls[2];
    }

    // ---- epilogue: normalize, split to hi/lo fp16 for out-proj ----
    const float inv0 = 1.f / l0;
    const float inv1 = 1.f / l1;
    const int b = bh >> 3, h = bh & 7;
    const int row0 = q0 + wrow + r0;
    const size_t off0 = ((size_t)(b * NN + row0)) * DD + h * DH;
    const size_t off1 = off0 + (size_t)8 * DD;
#pragma unroll
    for (int n = 0; n < 8; n++) {
        const int col = n * 8 + 2 * cB;
        uint32_t h0, lo0, h1, lo1;
        split2(o[n][0] * inv0, o[n][1] * inv0, h0, lo0);
        split2(o[n][2] * inv1, o[n][3] * inv1, h1, lo1);
        *(uint32_t*)(g_ah + off0 + col) = h0;
        *(uint32_t*)(g_al + off0 + col) = lo0;
        *(uint32_t*)(g_ah + off1 + col) = h1;
        *(uint32_t*)(g_al + off1 + col) = lo1;
    }
}

// ===========================================================================

extern "C" void kernel_launch(void* const* d_in, const int* in_sizes, int n_in,
                              void* d_out, int out_size)
{
    (void)in_sizes; (void)n_in; (void)out_size;
    const float* x  = (const float*)d_in[0];
    const float* Wq = (const float*)d_in[1];
    const float* Wk = (const float*)d_in[2];
    const float* Wv = (const float*)d_in[3];
    const float* Wo = (const float*)d_in[4];
    const float* bo = (const float*)d_in[5];
    float* out = (float*)d_out;

    cudaFuncSetAttribute(hgemm_kernel,
                         cudaFuncAttributeMaxDynamicSharedMemorySize, GEMM_SMEM);
    cudaFuncSetAttribute(attn_mma_kernel,
                         cudaFuncAttributeMaxDynamicSharedMemorySize, SM_TOT);

    // merged split conversions (x + 4 weights) in one launch
    conv_all_kernel<<<4096 + 4 * 256, 256>>>(x, Wq, Wk, Wv, Wo);

    // QKV projections (tensor cores, split-fp16)
    hgemm_kernel<<<dim3(4, 64, 3), 256, GEMM_SMEM>>>(-1, nullptr, nullptr);
    // Flash attention
    attn_mma_kernel<<<dim3(NN / 128, BB * HH), 256, SM_TOT>>>();
    // Output projection + bias
    hgemm_kernel<<<dim3(4, 64, 1), 256, GEMM_SMEM>>>(3, bo, out);
}

// round 13
// speedup vs baseline: 1.7829x; 1.1250x over previous
#include <cuda_runtime.h>
#include <cuda_fp16.h>
#include <cstdint>
#include <cstddef>

// Problem constants
#define BB 2
#define NN 4096
#define DD 512
#define HH 8
#define DH 64
#define SCALE_F 0.125f   // 64^-0.5
#define LOG2E_F 1.4426950408889634f

// Scratch (allocation-free rule: __device__ globals).
// NOTE: __device__ symbols must ONLY be referenced from device code.
__device__ __align__(16) __half g_xh[(size_t)BB * NN * DD];
__device__ __align__(16) __half g_xl[(size_t)BB * NN * DD];
__device__ __align__(16) __half g_wh[(size_t)4 * DD * DD];   // W hi only (lo term dropped)
__device__ __align__(16) __half g_qh [(size_t)BB * HH * NN * DH];
__device__ __align__(16) __half g_kh [(size_t)BB * HH * NN * DH];
__device__ __align__(16) __half g_vth[(size_t)BB * HH * NN * DH];
__device__ __align__(16) __half g_ah[(size_t)BB * NN * DD];
__device__ __align__(16) __half g_al[(size_t)BB * NN * DD];

// ===========================================================================
// Helpers (arch-neutral PTX only)
// ===========================================================================

__device__ __forceinline__ uint32_t smem_u32(const void* p) {
    uint32_t a;
    asm("{ .reg .u64 t; cvta.to.shared.u64 t, %1; cvt.u32.u64 %0, t; }"
        : "=r"(a) : "l"(p));
    return a;
}

__device__ __forceinline__ float ex2f(float x) {
    float y;
    asm("ex2.approx.ftz.f32 %0, %1;" : "=f"(y) : "f"(x));
    return y;
}

// D += A @ B, f32 accumulator
__device__ __forceinline__ void mma_f16(float* d, const uint32_t* a, const uint32_t* b) {
    asm volatile(
        "mma.sync.aligned.m16n8k16.row.col.f32.f16.f16.f32 "
        "{%0,%1,%2,%3}, {%4,%5,%6,%7}, {%8,%9}, {%0,%1,%2,%3};"
        : "+f"(d[0]), "+f"(d[1]), "+f"(d[2]), "+f"(d[3])
        : "r"(a[0]), "r"(a[1]), "r"(a[2]), "r"(a[3]), "r"(b[0]), "r"(b[1]));
}

// D += A @ B, f16 accumulator (D = 2x b32 = 4 halves)
__device__ __forceinline__ void mma_f16h(uint32_t* d, const uint32_t* a, const uint32_t* b) {
    asm volatile(
        "mma.sync.aligned.m16n8k16.row.col.f16.f16.f16.f16 "
        "{%0,%1}, {%2,%3,%4,%5}, {%6,%7}, {%0,%1};"
        : "+r"(d[0]), "+r"(d[1])
        : "r"(a[0]), "r"(a[1]), "r"(a[2]), "r"(a[3]), "r"(b[0]), "r"(b[1]));
}

__device__ __forceinline__ void cp_async16(uint32_t dst, const void* src) {
    asm volatile("cp.async.cg.shared.global [%0], [%1], 16;"
                 :: "r"(dst), "l"(src) : "memory");
}
#define CP_COMMIT() asm volatile("cp.async.commit_group;" ::: "memory")
#define CP_WAIT0()  asm volatile("cp.async.wait_group 0;" ::: "memory")

__device__ __forceinline__ uint32_t pack2(__half a, __half b) {
    __half2 h = __halves2half2(a, b);
    return *(uint32_t*)&h;
}

// split pair of floats into hi/lo fp16x2 words
__device__ __forceinline__ void split2(float a, float b, uint32_t& hi, uint32_t& lo) {
    __half ha = __float2half_rn(a), hb = __float2half_rn(b);
    hi = pack2(ha, hb);
    __half2 L = __floats2half2_rn(a - __half2float(ha), b - __half2float(hb));
    lo = *(uint32_t*)&L;
}

// P = exp2(d - m) in half2 domain, returns packed fp16x2 bits
__device__ __forceinline__ uint32_t p_h2(uint32_t d_bits, __half2 m2) {
    __half2 d = *(__half2*)&d_bits;
    __half2 p = h2exp2(__hsub2(d, m2));
    return *(uint32_t*)&p;
}

// XOR-swizzled LDS.32 from [row][64-half = 128B] tile
__device__ __forceinline__ uint32_t lds32(const char* base, uint32_t row, uint32_t chunk, uint32_t cB) {
    return *(const uint32_t*)(base + row * 128 + ((chunk ^ (row & 7u)) << 4) + cB * 4);
}

// ===========================================================================
// merged conversion kernel: x -> (hi,lo); weights -> hi only.
// grid: [0,4096) = x ; [4096, 4096+4*256) = Wq,Wk,Wv,Wo
// ===========================================================================
__global__ __launch_bounds__(256) void conv_all_kernel(
    const float* __restrict__ x,
    const float* __restrict__ Wq, const float* __restrict__ Wk,
    const float* __restrict__ Wv, const float* __restrict__ Wo)
{
    const int bid = blockIdx.x;
    if (bid < 4096) {
        const int idx = bid * 256 + threadIdx.x;
        float4 f = ((const float4*)x)[idx];
        uint32_t h0, l0, h1, l1;
        split2(f.x, f.y, h0, l0);
        split2(f.z, f.w, h1, l1);
        uint32_t* dh32 = (uint32_t*)g_xh;
        uint32_t* dl32 = (uint32_t*)g_xl;
        dh32[idx * 2 + 0] = h0;
        dh32[idx * 2 + 1] = h1;
        dl32[idx * 2 + 0] = l0;
        dl32[idx * 2 + 1] = l1;
    } else {
        const int w = (bid - 4096) >> 8;      // 0..3
        const float* src = (w == 0) ? Wq : (w == 1) ? Wk : (w == 2) ? Wv : Wo;
        const int idx = ((bid - 4096) & 255) * 256 + threadIdx.x;
        float4 f = ((const float4*)src)[idx];
        uint32_t h0, h1;
        __half2 a = __floats2half2_rn(f.x, f.y);
        __half2 b = __floats2half2_rn(f.z, f.w);
        h0 = *(uint32_t*)&a; h1 = *(uint32_t*)&b;
        uint32_t* dh32 = (uint32_t*)(g_wh + (size_t)w * DD * DD);
        dh32[idx * 2 + 0] = h0;
        dh32[idx * 2 + 1] = h1;
    }
}

// ===========================================================================
// Split-fp16 GEMM, 2 terms: C ≈ Ah·Bh + (activation-lo term).
//   z=0 Q, z=1 K: A=x(hi,lo) B=W(hi)       -> Ah·Bh + Al·Bh
//   z=2 V^T:      A=Wv(hi)  B=x(hi,lo)     -> Ah·Bh + Ah·Bl
//   z=3 out:      A=attn(hi,lo) B=Wo(hi)   -> Ah·Bh + Al·Bh
// (W-lo term dropped: adds ~1.7e-4 rel err per GEMM, saves 33% of mma.)
// smem: 2 stages x 3 tiles x [128 rows][128B] = 96KB
// ===========================================================================

#define GEMM_SMEM 98304

__global__ __launch_bounds__(256) void hgemm_kernel(
    int mode_arg, const float* __restrict__ bo, float* __restrict__ outp)
{
    extern __shared__ char smem[];
    const uint32_t sbase = smem_u32(smem);

    const int tid  = threadIdx.x;
    const int lane = tid & 31;
    const int warp = tid >> 5;
    const int r0   = lane >> 2;
    const int cB   = lane & 3;
    const int wm   = (warp >> 1) * 32;
    const int wn   = (warp & 1) * 64;
    const int bx   = blockIdx.x;
    const int by   = blockIdx.y;
    const int z    = (mode_arg < 0) ? (int)blockIdx.z : mode_arg;

    const __half *pa_h, *pb_h, *p_lo;
    size_t arow0, brow0;
    bool lo_on_b;
    if (z == 0)      { pa_h = g_xh; p_lo = g_xl; pb_h = g_wh;              lo_on_b = false; arow0 = (size_t)by * 128; brow0 = (size_t)bx * 128; }
    else if (z == 1) { pa_h = g_xh; p_lo = g_xl; pb_h = g_wh + 262144;     lo_on_b = false; arow0 = (size_t)by * 128; brow0 = (size_t)bx * 128; }
    else if (z == 2) { pa_h = g_wh + 2 * 262144; p_lo = g_xl; pb_h = g_xh; lo_on_b = true;  arow0 = (size_t)bx * 128; brow0 = (size_t)by * 128; }
    else             { pa_h = g_ah; p_lo = g_al; pb_h = g_wh + 3 * 262144; lo_on_b = false; arow0 = (size_t)by * 128; brow0 = (size_t)bx * 128; }
    const size_t lrow0 = lo_on_b ? brow0 : arow0;

    const int lrow = tid >> 1;
    const int c0l  = (tid & 1) * 4;

    auto issue = [&](int stage, int k0) {
        const uint32_t sw = ((uint32_t)lrow & 7u);
        const uint32_t rowoff = (uint32_t)lrow * 128u;
        const uint32_t st = sbase + stage * 49152;
        const __half* srcs[3] = {
            pa_h + (arow0 + lrow) * DD + k0,
            p_lo + (lrow0 + lrow) * DD + k0,
            pb_h + (brow0 + lrow) * DD + k0 };
#pragma unroll
        for (int tile = 0; tile < 3; tile++) {
            const uint32_t tbase = st + tile * 16384 + rowoff;
#pragma unroll
            for (int i = 0; i < 4; i++) {
                const uint32_t c = (uint32_t)(c0l + i);
                cp_async16(tbase + ((c ^ sw) << 4), srcs[tile] + c * 8);
            }
        }
    };

    float acc[2][8][4];
#pragma unroll
    for (int mf = 0; mf < 2; mf++)
#pragma unroll
        for (int nf = 0; nf < 8; nf++)
#pragma unroll
            for (int j = 0; j < 4; j++) acc[mf][nf][j] = 0.f;

    issue(0, 0);
    CP_COMMIT();

    for (int kc = 0; kc < 8; kc++) {
        CP_WAIT0();
        __syncthreads();
        if (kc + 1 < 8) { issue((kc + 1) & 1, (kc + 1) * 64); CP_COMMIT(); }

        const char* sA = smem + (kc & 1) * 49152;
        const char* sL = sA + 16384;
        const char* sB = sA + 32768;

#pragma unroll
        for (int ks = 0; ks < 4; ks++) {
            uint32_t ah[2][4], bh[8][2];
#pragma unroll
            for (int mf = 0; mf < 2; mf++) {
                const uint32_t ra = (uint32_t)(wm + mf * 16 + r0);
                ah[mf][0] = lds32(sA, ra,     2 * ks,     cB);
                ah[mf][1] = lds32(sA, ra + 8, 2 * ks,     cB);
                ah[mf][2] = lds32(sA, ra,     2 * ks + 1, cB);
                ah[mf][3] = lds32(sA, ra + 8, 2 * ks + 1, cB);
            }
#pragma unroll
            for (int nf = 0; nf < 8; nf++) {
                const uint32_t rb = (uint32_t)(wn + nf * 8 + r0);
                bh[nf][0] = lds32(sB, rb, 2 * ks,     cB);
                bh[nf][1] = lds32(sB, rb, 2 * ks + 1, cB);
            }
            // main term
#pragma unroll
            for (int mf = 0; mf < 2; mf++)
#pragma unroll
                for (int nf = 0; nf < 8; nf++)
                    mma_f16(acc[mf][nf], ah[mf], bh[nf]);

            // activation-lo term
            if (!lo_on_b) {
                uint32_t al[2][4];
#pragma unroll
                for (int mf = 0; mf < 2; mf++) {
                    const uint32_t ra = (uint32_t)(wm + mf * 16 + r0);
                    al[mf][0] = lds32(sL, ra,     2 * ks,     cB);
                    al[mf][1] = lds32(sL, ra + 8, 2 * ks,     cB);
                    al[mf][2] = lds32(sL, ra,     2 * ks + 1, cB);
                    al[mf][3] = lds32(sL, ra + 8, 2 * ks + 1, cB);
                }
#pragma unroll
                for (int mf = 0; mf < 2; mf++)
#pragma unroll
                    for (int nf = 0; nf < 8; nf++)
                        mma_f16(acc[mf][nf], al[mf], bh[nf]);
            } else {
                uint32_t bl[8][2];
#pragma unroll
                for (int nf = 0; nf < 8; nf++) {
                    const uint32_t rb = (uint32_t)(wn + nf * 8 + r0);
                    bl[nf][0] = lds32(sL, rb, 2 * ks,     cB);
                    bl[nf][1] = lds32(sL, rb, 2 * ks + 1, cB);
                }
#pragma unroll
                for (int mf = 0; mf < 2; mf++)
#pragma unroll
                    for (int nf = 0; nf < 8; nf++)
                        mma_f16(acc[mf][nf], ah[mf], bl[nf]);
            }
        }
    }

    if (z == 0 || z == 1) {
        __half* outq = (z == 0) ? g_qh : g_kh;
        const float sc = (z == 0) ? (SCALE_F * LOG2E_F) : 1.f;
#pragma unroll
        for (int mf = 0; mf < 2; mf++) {
            const int tokA = by * 128 + wm + mf * 16 + r0;
#pragma unroll
            for (int nf = 0; nf < 8; nf++) {
                const int oo = bx * 128 + wn + nf * 8 + 2 * cB;
                const int h = oo >> 6, dd = oo & 63;
#pragma unroll
                for (int half_ = 0; half_ < 2; half_++) {
                    const int tok = tokA + half_ * 8;
                    const int b = tok >> 12, n = tok & (NN - 1);
                    const float v0 = acc[mf][nf][2 * half_ + 0] * sc;
                    const float v1 = acc[mf][nf][2 * half_ + 1] * sc;
                    *(uint32_t*)(outq + (((size_t)(b * HH + h) * NN) + n) * DH + dd) =
                        pack2(__float2half_rn(v0), __float2half_rn(v1));
                }
            }
        }
    } else if (z == 2) {
#pragma unroll
        for (int mf = 0; mf < 2; mf++) {
            const int frA = bx * 128 + wm + mf * 16 + r0;
#pragma unroll
            for (int nf = 0; nf < 8; nf++) {
                const int tk = by * 128 + wn + nf * 8 + 2 * cB;
                const int b = tk >> 12, n = tk & (NN - 1);
#pragma unroll
                for (int half_ = 0; half_ < 2; half_++) {
                    const int fr = frA + half_ * 8;
                    const int h = fr >> 6, dd = fr & 63;
                    const float v0 = acc[mf][nf][2 * half_ + 0];
                    const float v1 = acc[mf][nf][2 * half_ + 1];
                    *(uint32_t*)(g_vth + (((size_t)(b * HH + h) * DH) + dd) * NN + n) =
                        pack2(__float2half_rn(v0), __float2half_rn(v1));
                }
            }
        }
    } else {
#pragma unroll
        for (int mf = 0; mf < 2; mf++) {
            const int tokA = by * 128 + wm + mf * 16 + r0;
#pragma unroll
            for (int nf = 0; nf < 8; nf++) {
                const int oo = bx * 128 + wn + nf * 8 + 2 * cB;
                const float b0 = bo[oo], b1 = bo[oo + 1];
#pragma unroll
                for (int half_ = 0; half_ < 2; half_++) {
                    const int tok = tokA + half_ * 8;
                    float2 v;
                    v.x = acc[mf][nf][2 * half_ + 0] + b0;
                    v.y = acc[mf][nf][2 * half_ + 1] + b1;
                    *(float2*)(outp + (size_t)tok * DD + oo) = v;
                }
            }
        }
    }
}

// ===========================================================================
// Flash attention (R10/R12-proven): QK f16-acc, half2 softmax, guarded
// rescale, l via ones-mma, PV f32-acc.
// ===========================================================================

#define SM_TOT 32768

__global__ void __launch_bounds__(256, 2) attn_mma_kernel()
{
    extern __shared__ char smem[];
    const uint32_t sbase = smem_u32(smem);

    const int tid  = threadIdx.x;
    const int lane = tid & 31;
    const int warp = tid >> 5;
    const int bh   = blockIdx.y;
    const int q0   = blockIdx.x * 128;
    const int wrow = warp * 16;
    const int r0   = lane >> 2;
    const int cB   = lane & 3;

    const __half* khg  = g_kh  + (size_t)bh * NN * DH;
    const __half* vthg = g_vth + (size_t)bh * NN * DH;

    const int rowL = tid >> 2;
    const int fq   = tid & 3;

    {
        const char* ksrc = (const char*)(khg + (size_t)rowL * DH);
        const char* vsrc = (const char*)(vthg + (size_t)rowL * NN);
        const uint32_t kdst = sbase + rowL * 128;
        const uint32_t vdst = sbase + 16384 + rowL * 128;
        const uint32_t sw = (uint32_t)(rowL & 7);
        cp_async16(kdst + (((uint32_t)fq       ^ sw) << 4), ksrc + fq * 16);
        cp_async16(kdst + (((uint32_t)(fq + 4) ^ sw) << 4), ksrc + (fq + 4) * 16);
        cp_async16(vdst + (((uint32_t)fq       ^ sw) << 4), vsrc + fq * 16);
        cp_async16(vdst + (((uint32_t)(fq + 4) ^ sw) << 4), vsrc + (fq + 4) * 16);
        CP_COMMIT();
    }

    uint32_t qa[4][4];
    {
        const __half* qg = g_qh + ((size_t)bh * NN + q0 + wrow + r0) * DH;
#pragma unroll
        for (int s4 = 0; s4 < 4; s4++) {
            qa[s4][0] = *(const uint32_t*)(qg + s4 * 16 + 2 * cB);
            qa[s4][1] = *(const uint32_t*)(qg + 8 * DH + s4 * 16 + 2 * cB);
            qa[s4][2] = *(const uint32_t*)(qg + s4 * 16 + 2 * cB + 8);
            qa[s4][3] = *(const uint32_t*)(qg + 8 * DH + s4 * 16 + 2 * cB + 8);
        }
    }

    float o[8][4];
#pragma unroll
    for (int n = 0; n < 8; n++)
#pragma unroll
        for (int j = 0; j < 4; j++) o[n][j] = 0.f;
    float m0 = -1e30f, m1 = -1e30f, l0 = 0.f, l1 = 0.f;

    const uint32_t ones[2] = {0x3C003C00u, 0x3C003C00u};

    for (int t = 0; t < NN / 64; t++) {
        CP_WAIT0();
        __syncthreads();

        if (t + 1 < NN / 64) {
            const int buf = (t + 1) & 1;
            const char* ksrc = (const char*)(khg + ((size_t)(t + 1) * 64 + rowL) * DH);
            const char* vsrc = (const char*)(vthg + (size_t)rowL * NN + (t + 1) * 64);
            const uint32_t kdst = sbase + buf * 8192 + rowL * 128;
            const uint32_t vdst = sbase + 16384 + buf * 8192 + rowL * 128;
            const uint32_t sw = (uint32_t)(rowL & 7);
            cp_async16(kdst + (((uint32_t)fq       ^ sw) << 4), ksrc + fq * 16);
            cp_async16(kdst + (((uint32_t)(fq + 4) ^ sw) << 4), ksrc + (fq + 4) * 16);
            cp_async16(vdst + (((uint32_t)fq       ^ sw) << 4), vsrc + fq * 16);
            cp_async16(vdst + (((uint32_t)(fq + 4) ^ sw) << 4), vsrc + (fq + 4) * 16);
            CP_COMMIT();
        }

        const char* sK = smem + (t & 1) * 8192;
        const char* sV = smem + 16384 + (t & 1) * 8192;

        // ---- S = Q @ K^T, f16 accumulator ----
        uint32_t sc[8][2];
#pragma unroll
        for (int n = 0; n < 8; n++) { sc[n][0] = 0u; sc[n][1] = 0u; }

#pragma unroll
        for (int s4 = 0; s4 < 4; s4++) {
#pragma unroll
            for (int n = 0; n < 8; n++) {
                const uint32_t row = (uint32_t)(n * 8 + r0);
                uint32_t b[2];
                b[0] = lds32(sK, row, 2 * s4,     (uint32_t)cB);
                b[1] = lds32(sK, row, 2 * s4 + 1, (uint32_t)cB);
                mma_f16h(sc[n], qa[s4], b);
            }
        }

        // ---- online softmax, half2 domain ----
        __half2 hx0 = *(__half2*)&sc[0][0];
        __half2 hx1 = *(__half2*)&sc[0][1];
#pragma unroll
        for (int n = 1; n < 8; n++) {
            hx0 = __hmax2(hx0, *(__half2*)&sc[n][0]);
            hx1 = __hmax2(hx1, *(__half2*)&sc[n][1]);
        }
        float mx0 = fmaxf(__low2float(hx0), __high2float(hx0));
        float mx1 = fmaxf(__low2float(hx1), __high2float(hx1));
        mx0 = fmaxf(mx0, __shfl_xor_sync(0xffffffffu, mx0, 1));
        mx0 = fmaxf(mx0, __shfl_xor_sync(0xffffffffu, mx0, 2));
        mx1 = fmaxf(mx1, __shfl_xor_sync(0xffffffffu, mx1, 1));
        mx1 = fmaxf(mx1, __shfl_xor_sync(0xffffffffu, mx1, 2));

        if (mx0 > m0) {
            const float a0 = ex2f(m0 - mx0);
            l0 *= a0;
#pragma unroll
            for (int n = 0; n < 8; n++) { o[n][0] *= a0; o[n][1] *= a0; }
            m0 = mx0;
        }
        if (mx1 > m1) {
            const float a1 = ex2f(m1 - mx1);
            l1 *= a1;
#pragma unroll
            for (int n = 0; n < 8; n++) { o[n][2] *= a1; o[n][3] *= a1; }
            m1 = mx1;
        }

        const __half2 m0h2 = __floats2half2_rn(m0, m0);
        const __half2 m1h2 = __floats2half2_rn(m1, m1);

        // ---- P = exp2(S - m); O += P @ V; l via ones-mma ----
        float ls[4] = {0.f, 0.f, 0.f, 0.f};
#pragma unroll
        for (int s4 = 0; s4 < 4; s4++) {
            uint32_t pa[4];
            pa[0] = p_h2(sc[2 * s4][0],     m0h2);
            pa[1] = p_h2(sc[2 * s4][1],     m1h2);
            pa[2] = p_h2(sc[2 * s4 + 1][0], m0h2);
            pa[3] = p_h2(sc[2 * s4 + 1][1], m1h2);
            mma_f16(ls, pa, ones);
#pragma unroll
            for (int n = 0; n < 8; n++) {
                const uint32_t row = (uint32_t)(n * 8 + r0);
                uint32_t b[2];
                b[0] = lds32(sV, row, 2 * s4,     (uint32_t)cB);
                b[1] = lds32(sV, row, 2 * s4 + 1, (uint32_t)cB);
                mma_f16(o[n], pa, b);
            }
        }
        l0 += ls[0];
        l1 += ls[2];
    }

    // ---- epilogue: normalize, split to hi/lo fp16 for out-proj ----
    const float inv0 = 1.f / l0;
    const float inv1 = 1.f / l1;
    const int b = bh >> 3, h = bh & 7;
    const int row0 = q0 + wrow + r0;
    const size_t off0 = ((size_t)(b * NN + row0)) * DD + h * DH;
    const size_t off1 = off0 + (size_t)8 * DD;
#pragma unroll
    for (int n = 0; n < 8; n++) {
        const int col = n * 8 + 2 * cB;
        uint32_t h0, lo0, h1, lo1;
        split2(o[n][0] * inv0, o[n][1] * inv0, h0, lo0);
        split2(o[n][2] * inv1, o[n][3] * inv1, h1, lo1);
        *(uint32_t*)(g_ah + off0 + col) = h0;
        *(uint32_t*)(g_al + off0 + col) = lo0;
        *(uint32_t*)(g_ah + off1 + col) = h1;
        *(uint32_t*)(g_al + off1 + col) = lo1;
    }
}

// ===========================================================================

extern "C" void kernel_launch(void* const* d_in, const int* in_sizes, int n_in,
                              void* d_out, int out_size)
{
    (void)in_sizes; (void)n_in; (void)out_size;
    const float* x  = (const float*)d_in[0];
    const float* Wq = (const float*)d_in[1];
    const float* Wk = (const float*)d_in[2];
    const float* Wv = (const float*)d_in[3];
    const float* Wo = (const float*)d_in[4];
    const float* bo = (const float*)d_in[5];
    float* out = (float*)d_out;

    cudaFuncSetAttribute(hgemm_kernel,
                         cudaFuncAttributeMaxDynamicSharedMemorySize, GEMM_SMEM);
    cudaFuncSetAttribute(attn_mma_kernel,
                         cudaFuncAttributeMaxDynamicSharedMemorySize, SM_TOT);

    // merged split conversions (x hi/lo + 4 weight hi) in one launch
    conv_all_kernel<<<4096 + 4 * 256, 256>>>(x, Wq, Wk, Wv, Wo);

    // QKV projections (tensor cores, 2-term split-fp16)
    hgemm_kernel<<<dim3(4, 64, 3), 256, GEMM_SMEM>>>(-1, nullptr, nullptr);
    // Flash attention
    attn_mma_kernel<<<dim3(NN / 128, BB * HH), 256, SM_TOT>>>();
    // Output projection + bias
    hgemm_kernel<<<dim3(4, 64, 1), 256, GEMM_SMEM>>>(3, bo, out);
}

// round 14
// speedup vs baseline: 2.0448x; 1.1469x over previous
#include <cuda_runtime.h>
#include <cuda_fp16.h>
#include <cstdint>
#include <cstddef>

// Problem constants
#define BB 2
#define NN 4096
#define DD 512
#define HH 8
#define DH 64
#define SCALE_F 0.125f   // 64^-0.5
#define LOG2E_F 1.4426950408889634f

// Scratch (allocation-free rule: __device__ globals).
// NOTE: __device__ symbols must ONLY be referenced from device code.
__device__ __align__(16) __half g_xh[(size_t)BB * NN * DD];
__device__ __align__(16) __half g_xl[(size_t)BB * NN * DD];   // x lo (only used by... nothing now; kept for attn out path symmetry)
__device__ __align__(16) __half g_wh[(size_t)4 * DD * DD];    // W hi only
__device__ __align__(16) __half g_qh [(size_t)BB * HH * NN * DH];
__device__ __align__(16) __half g_kh [(size_t)BB * HH * NN * DH];
__device__ __align__(16) __half g_vth[(size_t)BB * HH * NN * DH];
__device__ __align__(16) __half g_ah[(size_t)BB * NN * DD];
__device__ __align__(16) __half g_al[(size_t)BB * NN * DD];

// ===========================================================================
// Helpers (arch-neutral PTX only)
// ===========================================================================

__device__ __forceinline__ uint32_t smem_u32(const void* p) {
    uint32_t a;
    asm("{ .reg .u64 t; cvta.to.shared.u64 t, %1; cvt.u32.u64 %0, t; }"
        : "=r"(a) : "l"(p));
    return a;
}

__device__ __forceinline__ float ex2f(float x) {
    float y;
    asm("ex2.approx.ftz.f32 %0, %1;" : "=f"(y) : "f"(x));
    return y;
}

// D += A @ B, f32 accumulator
__device__ __forceinline__ void mma_f16(float* d, const uint32_t* a, const uint32_t* b) {
    asm volatile(
        "mma.sync.aligned.m16n8k16.row.col.f32.f16.f16.f32 "
        "{%0,%1,%2,%3}, {%4,%5,%6,%7}, {%8,%9}, {%0,%1,%2,%3};"
        : "+f"(d[0]), "+f"(d[1]), "+f"(d[2]), "+f"(d[3])
        : "r"(a[0]), "r"(a[1]), "r"(a[2]), "r"(a[3]), "r"(b[0]), "r"(b[1]));
}

// D += A @ B, f16 accumulator (D = 2x b32 = 4 halves)
__device__ __forceinline__ void mma_f16h(uint32_t* d, const uint32_t* a, const uint32_t* b) {
    asm volatile(
        "mma.sync.aligned.m16n8k16.row.col.f16.f16.f16.f16 "
        "{%0,%1}, {%2,%3,%4,%5}, {%6,%7}, {%0,%1};"
        : "+r"(d[0]), "+r"(d[1])
        : "r"(a[0]), "r"(a[1]), "r"(a[2]), "r"(a[3]), "r"(b[0]), "r"(b[1]));
}

__device__ __forceinline__ void cp_async16(uint32_t dst, const void* src) {
    asm volatile("cp.async.cg.shared.global [%0], [%1], 16;"
                 :: "r"(dst), "l"(src) : "memory");
}
#define CP_COMMIT() asm volatile("cp.async.commit_group;" ::: "memory")
#define CP_WAIT0()  asm volatile("cp.async.wait_group 0;" ::: "memory")

__device__ __forceinline__ uint32_t pack2(__half a, __half b) {
    __half2 h = __halves2half2(a, b);
    return *(uint32_t*)&h;
}

// split pair of floats into hi/lo fp16x2 words
__device__ __forceinline__ void split2(float a, float b, uint32_t& hi, uint32_t& lo) {
    __half ha = __float2half_rn(a), hb = __float2half_rn(b);
    hi = pack2(ha, hb);
    __half2 L = __floats2half2_rn(a - __half2float(ha), b - __half2float(hb));
    lo = *(uint32_t*)&L;
}

// P = exp2(d - m) in half2 domain, returns packed fp16x2 bits
__device__ __forceinline__ uint32_t p_h2(uint32_t d_bits, __half2 m2) {
    __half2 d = *(__half2*)&d_bits;
    __half2 p = h2exp2(__hsub2(d, m2));
    return *(uint32_t*)&p;
}

// XOR-swizzled LDS.32 from [row][64-half = 128B] tile
__device__ __forceinline__ uint32_t lds32(const char* base, uint32_t row, uint32_t chunk, uint32_t cB) {
    return *(const uint32_t*)(base + row * 128 + ((chunk ^ (row & 7u)) << 4) + cB * 4);
}

// ===========================================================================
// merged conversion kernel: x -> hi (fp16); weights -> hi (fp16).
// (x-lo no longer consumed by any GEMM; attention out hi/lo produced by attn.)
// grid: [0,4096) = x ; [4096, 4096+4*256) = Wq,Wk,Wv,Wo
// ===========================================================================
__global__ __launch_bounds__(256) void conv_all_kernel(
    const float* __restrict__ x,
    const float* __restrict__ Wq, const float* __restrict__ Wk,
    const float* __restrict__ Wv, const float* __restrict__ Wo)
{
    const int bid = blockIdx.x;
    const float* src;
    uint32_t* dh32;
    int idx;
    if (bid < 4096) {
        src = x; dh32 = (uint32_t*)g_xh;
        idx = bid * 256 + threadIdx.x;
    } else {
        const int w = (bid - 4096) >> 8;
        src = (w == 0) ? Wq : (w == 1) ? Wk : (w == 2) ? Wv : Wo;
        dh32 = (uint32_t*)(g_wh + (size_t)w * DD * DD);
        idx = ((bid - 4096) & 255) * 256 + threadIdx.x;
    }
    float4 f = ((const float4*)src)[idx];
    __half2 a = __floats2half2_rn(f.x, f.y);
    __half2 b = __floats2half2_rn(f.z, f.w);
    dh32[idx * 2 + 0] = *(uint32_t*)&a;
    dh32[idx * 2 + 1] = *(uint32_t*)&b;
}

// ===========================================================================
// fp16 GEMM.
//   z=0 Q, z=1 K: C = x_h @ W_h^T               (1 term; result stored fp16)
//   z=2 V^T:      C = Wv_h @ x_h^T              (1 term; result stored fp16)
//   z=3 out:      C = (a_h + a_l) @ Wo_h^T + bo (2 terms; result is final f32)
// smem: 2 stages x 3 tiles x [128 rows][128B] = 96KB (lo tile unused for z<3)
// ===========================================================================

#define GEMM_SMEM 98304

__global__ __launch_bounds__(256) void hgemm_kernel(
    int mode_arg, const float* __restrict__ bo, float* __restrict__ outp)
{
    extern __shared__ char smem[];
    const uint32_t sbase = smem_u32(smem);

    const int tid  = threadIdx.x;
    const int lane = tid & 31;
    const int warp = tid >> 5;
    const int r0   = lane >> 2;
    const int cB   = lane & 3;
    const int wm   = (warp >> 1) * 32;
    const int wn   = (warp & 1) * 64;
    const int bx   = blockIdx.x;
    const int by   = blockIdx.y;
    const int z    = (mode_arg < 0) ? (int)blockIdx.z : mode_arg;
    const bool use_lo = (z == 3);

    const __half *pa_h, *pb_h, *p_lo;
    size_t arow0, brow0;
    if (z == 0)      { pa_h = g_xh; p_lo = g_xh; pb_h = g_wh;              arow0 = (size_t)by * 128; brow0 = (size_t)bx * 128; }
    else if (z == 1) { pa_h = g_xh; p_lo = g_xh; pb_h = g_wh + 262144;     arow0 = (size_t)by * 128; brow0 = (size_t)bx * 128; }
    else if (z == 2) { pa_h = g_wh + 2 * 262144; p_lo = g_xh; pb_h = g_xh; arow0 = (size_t)bx * 128; brow0 = (size_t)by * 128; }
    else             { pa_h = g_ah; p_lo = g_al; pb_h = g_wh + 3 * 262144; arow0 = (size_t)by * 128; brow0 = (size_t)bx * 128; }

    const int lrow = tid >> 1;
    const int c0l  = (tid & 1) * 4;

    auto issue = [&](int stage, int k0) {
        const uint32_t sw = ((uint32_t)lrow & 7u);
        const uint32_t rowoff = (uint32_t)lrow * 128u;
        const uint32_t st = sbase + stage * 49152;
        const __half* sA = pa_h + (arow0 + lrow) * DD + k0;
        const __half* sB = pb_h + (brow0 + lrow) * DD + k0;
#pragma unroll
        for (int i = 0; i < 4; i++) {
            const uint32_t c = (uint32_t)(c0l + i);
            const uint32_t so = ((c ^ sw) << 4) + rowoff;
            cp_async16(st + so,          sA + c * 8);
            cp_async16(st + 32768 + so,  sB + c * 8);
        }
        if (use_lo) {
            const __half* sL = p_lo + (arow0 + lrow) * DD + k0;
#pragma unroll
            for (int i = 0; i < 4; i++) {
                const uint32_t c = (uint32_t)(c0l + i);
                cp_async16(st + 16384 + ((c ^ sw) << 4) + rowoff, sL + c * 8);
            }
        }
    };

    float acc[2][8][4];
#pragma unroll
    for (int mf = 0; mf < 2; mf++)
#pragma unroll
        for (int nf = 0; nf < 8; nf++)
#pragma unroll
            for (int j = 0; j < 4; j++) acc[mf][nf][j] = 0.f;

    issue(0, 0);
    CP_COMMIT();

    for (int kc = 0; kc < 8; kc++) {
        CP_WAIT0();
        __syncthreads();
        if (kc + 1 < 8) { issue((kc + 1) & 1, (kc + 1) * 64); CP_COMMIT(); }

        const char* sA = smem + (kc & 1) * 49152;
        const char* sL = sA + 16384;
        const char* sB = sA + 32768;

#pragma unroll
        for (int ks = 0; ks < 4; ks++) {
            uint32_t ah[2][4], bh[8][2];
#pragma unroll
            for (int mf = 0; mf < 2; mf++) {
                const uint32_t ra = (uint32_t)(wm + mf * 16 + r0);
                ah[mf][0] = lds32(sA, ra,     2 * ks,     cB);
                ah[mf][1] = lds32(sA, ra + 8, 2 * ks,     cB);
                ah[mf][2] = lds32(sA, ra,     2 * ks + 1, cB);
                ah[mf][3] = lds32(sA, ra + 8, 2 * ks + 1, cB);
            }
#pragma unroll
            for (int nf = 0; nf < 8; nf++) {
                const uint32_t rb = (uint32_t)(wn + nf * 8 + r0);
                bh[nf][0] = lds32(sB, rb, 2 * ks,     cB);
                bh[nf][1] = lds32(sB, rb, 2 * ks + 1, cB);
            }
#pragma unroll
            for (int mf = 0; mf < 2; mf++)
#pragma unroll
                for (int nf = 0; nf < 8; nf++)
                    mma_f16(acc[mf][nf], ah[mf], bh[nf]);

            if (use_lo) {
                uint32_t al[2][4];
#pragma unroll
                for (int mf = 0; mf < 2; mf++) {
                    const uint32_t ra = (uint32_t)(wm + mf * 16 + r0);
                    al[mf][0] = lds32(sL, ra,     2 * ks,     cB);
                    al[mf][1] = lds32(sL, ra + 8, 2 * ks,     cB);
                    al[mf][2] = lds32(sL, ra,     2 * ks + 1, cB);
                    al[mf][3] = lds32(sL, ra + 8, 2 * ks + 1, cB);
                }
#pragma unroll
                for (int mf = 0; mf < 2; mf++)
#pragma unroll
                    for (int nf = 0; nf < 8; nf++)
                        mma_f16(acc[mf][nf], al[mf], bh[nf]);
            }
        }
    }

    if (z == 0 || z == 1) {
        __half* outq = (z == 0) ? g_qh : g_kh;
        const float sc = (z == 0) ? (SCALE_F * LOG2E_F) : 1.f;
#pragma unroll
        for (int mf = 0; mf < 2; mf++) {
            const int tokA = by * 128 + wm + mf * 16 + r0;
#pragma unroll
            for (int nf = 0; nf < 8; nf++) {
                const int oo = bx * 128 + wn + nf * 8 + 2 * cB;
                const int h = oo >> 6, dd = oo & 63;
#pragma unroll
                for (int half_ = 0; half_ < 2; half_++) {
                    const int tok = tokA + half_ * 8;
                    const int b = tok >> 12, n = tok & (NN - 1);
                    const float v0 = acc[mf][nf][2 * half_ + 0] * sc;
                    const float v1 = acc[mf][nf][2 * half_ + 1] * sc;
                    *(uint32_t*)(outq + (((size_t)(b * HH + h) * NN) + n) * DH + dd) =
                        pack2(__float2half_rn(v0), __float2half_rn(v1));
                }
            }
        }
    } else if (z == 2) {
#pragma unroll
        for (int mf = 0; mf < 2; mf++) {
            const int frA = bx * 128 + wm + mf * 16 + r0;
#pragma unroll
            for (int nf = 0; nf < 8; nf++) {
                const int tk = by * 128 + wn + nf * 8 + 2 * cB;
                const int b = tk >> 12, n = tk & (NN - 1);
#pragma unroll
                for (int half_ = 0; half_ < 2; half_++) {
                    const int fr = frA + half_ * 8;
                    const int h = fr >> 6, dd = fr & 63;
                    const float v0 = acc[mf][nf][2 * half_ + 0];
                    const float v1 = acc[mf][nf][2 * half_ + 1];
                    *(uint32_t*)(g_vth + (((size_t)(b * HH + h) * DH) + dd) * NN + n) =
                        pack2(__float2half_rn(v0), __float2half_rn(v1));
                }
            }
        }
    } else {
#pragma unroll
        for (int mf = 0; mf < 2; mf++) {
            const int tokA = by * 128 + wm + mf * 16 + r0;
#pragma unroll
            for (int nf = 0; nf < 8; nf++) {
                const int oo = bx * 128 + wn + nf * 8 + 2 * cB;
                const float b0 = bo[oo], b1 = bo[oo + 1];
#pragma unroll
                for (int half_ = 0; half_ < 2; half_++) {
                    const int tok = tokA + half_ * 8;
                    float2 v;
                    v.x = acc[mf][nf][2 * half_ + 0] + b0;
                    v.y = acc[mf][nf][2 * half_ + 1] + b1;
                    *(float2*)(outp + (size_t)tok * DD + oo) = v;
                }
            }
        }
    }
}

// ===========================================================================
// Flash attention (R10/R12-proven, untouched): QK f16-acc, half2 softmax,
// guarded rescale, l via ones-mma, PV f32-acc.
// ===========================================================================

#define SM_TOT 32768

__global__ void __launch_bounds__(256, 2) attn_mma_kernel()
{
    extern __shared__ char smem[];
    const uint32_t sbase = smem_u32(smem);

    const int tid  = threadIdx.x;
    const int lane = tid & 31;
    const int warp = tid >> 5;
    const int bh   = blockIdx.y;
    const int q0   = blockIdx.x * 128;
    const int wrow = warp * 16;
    const int r0   = lane >> 2;
    const int cB   = lane & 3;

    const __half* khg  = g_kh  + (size_t)bh * NN * DH;
    const __half* vthg = g_vth + (size_t)bh * NN * DH;

    const int rowL = tid >> 2;
    const int fq   = tid & 3;

    {
        const char* ksrc = (const char*)(khg + (size_t)rowL * DH);
        const char* vsrc = (const char*)(vthg + (size_t)rowL * NN);
        const uint32_t kdst = sbase + rowL * 128;
        const uint32_t vdst = sbase + 16384 + rowL * 128;
        const uint32_t sw = (uint32_t)(rowL & 7);
        cp_async16(kdst + (((uint32_t)fq       ^ sw) << 4), ksrc + fq * 16);
        cp_async16(kdst + (((uint32_t)(fq + 4) ^ sw) << 4), ksrc + (fq + 4) * 16);
        cp_async16(vdst + (((uint32_t)fq       ^ sw) << 4), vsrc + fq * 16);
        cp_async16(vdst + (((uint32_t)(fq + 4) ^ sw) << 4), vsrc + (fq + 4) * 16);
        CP_COMMIT();
    }

    uint32_t qa[4][4];
    {
        const __half* qg = g_qh + ((size_t)bh * NN + q0 + wrow + r0) * DH;
#pragma unroll
        for (int s4 = 0; s4 < 4; s4++) {
            qa[s4][0] = *(const uint32_t*)(qg + s4 * 16 + 2 * cB);
            qa[s4][1] = *(const uint32_t*)(qg + 8 * DH + s4 * 16 + 2 * cB);
            qa[s4][2] = *(const uint32_t*)(qg + s4 * 16 + 2 * cB + 8);
            qa[s4][3] = *(const uint32_t*)(qg + 8 * DH + s4 * 16 + 2 * cB + 8);
        }
    }

    float o[8][4];
#pragma unroll
    for (int n = 0; n < 8; n++)
#pragma unroll
        for (int j = 0; j < 4; j++) o[n][j] = 0.f;
    float m0 = -1e30f, m1 = -1e30f, l0 = 0.f, l1 = 0.f;

    const uint32_t ones[2] = {0x3C003C00u, 0x3C003C00u};

    for (int t = 0; t < NN / 64; t++) {
        CP_WAIT0();
        __syncthreads();

        if (t + 1 < NN / 64) {
            const int buf = (t + 1) & 1;
            const char* ksrc = (const char*)(khg + ((size_t)(t + 1) * 64 + rowL) * DH);
            const char* vsrc = (const char*)(vthg + (size_t)rowL * NN + (t + 1) * 64);
            const uint32_t kdst = sbase + buf * 8192 + rowL * 128;
            const uint32_t vdst = sbase + 16384 + buf * 8192 + rowL * 128;
            const uint32_t sw = (uint32_t)(rowL & 7);
            cp_async16(kdst + (((uint32_t)fq       ^ sw) << 4), ksrc + fq * 16);
            cp_async16(kdst + (((uint32_t)(fq + 4) ^ sw) << 4), ksrc + (fq + 4) * 16);
            cp_async16(vdst + (((uint32_t)fq       ^ sw) << 4), vsrc + fq * 16);
            cp_async16(vdst + (((uint32_t)(fq + 4) ^ sw) << 4), vsrc + (fq + 4) * 16);
            CP_COMMIT();
        }

        const char* sK = smem + (t & 1) * 8192;
        const char* sV = smem + 16384 + (t & 1) * 8192;

        // ---- S = Q @ K^T, f16 accumulator ----
        uint32_t sc[8][2];
#pragma unroll
        for (int n = 0; n < 8; n++) { sc[n][0] = 0u; sc[n][1] = 0u; }

#pragma unroll
        for (int s4 = 0; s4 < 4; s4++) {
#pragma unroll
            for (int n = 0; n < 8; n++) {
                const uint32_t row = (uint32_t)(n * 8 + r0);
                uint32_t b[2];
                b[0] = lds32(sK, row, 2 * s4,     (uint32_t)cB);
                b[1] = lds32(sK, row, 2 * s4 + 1, (uint32_t)cB);
                mma_f16h(sc[n], qa[s4], b);
            }
        }

        // ---- online softmax, half2 domain ----
        __half2 hx0 = *(__half2*)&sc[0][0];
        __half2 hx1 = *(__half2*)&sc[0][1];
#pragma unroll
        for (int n = 1; n < 8; n++) {
            hx0 = __hmax2(hx0, *(__half2*)&sc[n][0]);
            hx1 = __hmax2(hx1, *(__half2*)&sc[n][1]);
        }
        float mx0 = fmaxf(__low2float(hx0), __high2float(hx0));
        float mx1 = fmaxf(__low2float(hx1), __high2float(hx1));
        mx0 = fmaxf(mx0, __shfl_xor_sync(0xffffffffu, mx0, 1));
        mx0 = fmaxf(mx0, __shfl_xor_sync(0xffffffffu, mx0, 2));
        mx1 = fmaxf(mx1, __shfl_xor_sync(0xffffffffu, mx1, 1));
        mx1 = fmaxf(mx1, __shfl_xor_sync(0xffffffffu, mx1, 2));

        if (mx0 > m0) {
            const float a0 = ex2f(m0 - mx0);
            l0 *= a0;
#pragma unroll
            for (int n = 0; n < 8; n++) { o[n][0] *= a0; o[n][1] *= a0; }
            m0 = mx0;
        }
        if (mx1 > m1) {
            const float a1 = ex2f(m1 - mx1);
            l1 *= a1;
#pragma unroll
            for (int n = 0; n < 8; n++) { o[n][2] *= a1; o[n][3] *= a1; }
            m1 = mx1;
        }

        const __half2 m0h2 = __floats2half2_rn(m0, m0);
        const __half2 m1h2 = __floats2half2_rn(m1, m1);

        // ---- P = exp2(S - m); O += P @ V; l via ones-mma ----
        float ls[4] = {0.f, 0.f, 0.f, 0.f};
#pragma unroll
        for (int s4 = 0; s4 < 4; s4++) {
            uint32_t pa[4];
            pa[0] = p_h2(sc[2 * s4][0],     m0h2);
            pa[1] = p_h2(sc[2 * s4][1],     m1h2);
            pa[2] = p_h2(sc[2 * s4 + 1][0], m0h2);
            pa[3] = p_h2(sc[2 * s4 + 1][1], m1h2);
            mma_f16(ls, pa, ones);
#pragma unroll
            for (int n = 0; n < 8; n++) {
                const uint32_t row = (uint32_t)(n * 8 + r0);
                uint32_t b[2];
                b[0] = lds32(sV, row, 2 * s4,     (uint32_t)cB);
                b[1] = lds32(sV, row, 2 * s4 + 1, (uint32_t)cB);
                mma_f16(o[n], pa, b);
            }
        }
        l0 += ls[0];
        l1 += ls[2];
    }

    // ---- epilogue: normalize, split to hi/lo fp16 for out-proj ----
    const float inv0 = 1.f / l0;
    const float inv1 = 1.f / l1;
    const int b = bh >> 3, h = bh & 7;
    const int row0 = q0 + wrow + r0;
    const size_t off0 = ((size_t)(b * NN + row0)) * DD + h * DH;
    const size_t off1 = off0 + (size_t)8 * DD;
#pragma unroll
    for (int n = 0; n < 8; n++) {
        const int col = n * 8 + 2 * cB;
        uint32_t h0, lo0, h1, lo1;
        split2(o[n][0] * inv0, o[n][1] * inv0, h0, lo0);
        split2(o[n][2] * inv1, o[n][3] * inv1, h1, lo1);
        *(uint32_t*)(g_ah + off0 + col) = h0;
        *(uint32_t*)(g_al + off0 + col) = lo0;
        *(uint32_t*)(g_ah + off1 + col) = h1;
        *(uint32_t*)(g_al + off1 + col) = lo1;
    }
}

// ===========================================================================

extern "C" void kernel_launch(void* const* d_in, const int* in_sizes, int n_in,
                              void* d_out, int out_size)
{
    (void)in_sizes; (void)n_in; (void)out_size;
    const float* x  = (const float*)d_in[0];
    const float* Wq = (const float*)d_in[1];
    const float* Wk = (const float*)d_in[2];
    const float* Wv = (const float*)d_in[3];
    const float* Wo = (const float*)d_in[4];
    const float* bo = (const float*)d_in[5];
    float* out = (float*)d_out;

    cudaFuncSetAttribute(hgemm_kernel,
                         cudaFuncAttributeMaxDynamicSharedMemorySize, GEMM_SMEM);
    cudaFuncSetAttribute(attn_mma_kernel,
                         cudaFuncAttributeMaxDynamicSharedMemorySize, SM_TOT);

    // merged conversions (x hi + 4 weight hi) in one launch
    conv_all_kernel<<<4096 + 4 * 256, 256>>>(x, Wq, Wk, Wv, Wo);

    // QKV projections (1-term fp16 — outputs are fp16-quantized anyway)
    hgemm_kernel<<<dim3(4, 64, 3), 256, GEMM_SMEM>>>(-1, nullptr, nullptr);
    // Flash attention
    attn_mma_kernel<<<dim3(NN / 128, BB * HH), 256, SM_TOT>>>();
    // Output projection + bias (2-term split: final f32 output)
    hgemm_kernel<<<dim3(4, 64, 1), 256, GEMM_SMEM>>>(3, bo, out);
}

// round 15
// speedup vs baseline: 2.1711x; 1.0617x over previous
#include <cuda_runtime.h>
#include <cuda_fp16.h>
#include <cstdint>
#include <cstddef>

// Problem constants
#define BB 2
#define NN 4096
#define DD 512
#define HH 8
#define DH 64
#define SCALE_F 0.125f   // 64^-0.5
#define LOG2E_F 1.4426950408889634f

// Scratch (allocation-free rule: __device__ globals).
// NOTE: __device__ symbols must ONLY be referenced from device code.
__device__ __align__(16) __half g_xh[(size_t)BB * NN * DD];
__device__ __align__(16) __half g_wh[(size_t)4 * DD * DD];    // Wq,Wk,Wv,Wo (fp16)
__device__ __align__(16) __half g_qh [(size_t)BB * HH * NN * DH];
__device__ __align__(16) __half g_kh [(size_t)BB * HH * NN * DH];
__device__ __align__(16) __half g_vth[(size_t)BB * HH * NN * DH];
__device__ __align__(16) __half g_ah[(size_t)BB * NN * DD];   // attention out (fp16)

// ===========================================================================
// Helpers (arch-neutral PTX only)
// ===========================================================================

__device__ __forceinline__ uint32_t smem_u32(const void* p) {
    uint32_t a;
    asm("{ .reg .u64 t; cvta.to.shared.u64 t, %1; cvt.u32.u64 %0, t; }"
        : "=r"(a) : "l"(p));
    return a;
}

__device__ __forceinline__ float ex2f(float x) {
    float y;
    asm("ex2.approx.ftz.f32 %0, %1;" : "=f"(y) : "f"(x));
    return y;
}

// D += A @ B, f32 accumulator
__device__ __forceinline__ void mma_f16(float* d, const uint32_t* a, const uint32_t* b) {
    asm volatile(
        "mma.sync.aligned.m16n8k16.row.col.f32.f16.f16.f32 "
        "{%0,%1,%2,%3}, {%4,%5,%6,%7}, {%8,%9}, {%0,%1,%2,%3};"
        : "+f"(d[0]), "+f"(d[1]), "+f"(d[2]), "+f"(d[3])
        : "r"(a[0]), "r"(a[1]), "r"(a[2]), "r"(a[3]), "r"(b[0]), "r"(b[1]));
}

// D += A @ B, f16 accumulator (D = 2x b32 = 4 halves)
__device__ __forceinline__ void mma_f16h(uint32_t* d, const uint32_t* a, const uint32_t* b) {
    asm volatile(
        "mma.sync.aligned.m16n8k16.row.col.f16.f16.f16.f16 "
        "{%0,%1}, {%2,%3,%4,%5}, {%6,%7}, {%0,%1};"
        : "+r"(d[0]), "+r"(d[1])
        : "r"(a[0]), "r"(a[1]), "r"(a[2]), "r"(a[3]), "r"(b[0]), "r"(b[1]));
}

__device__ __forceinline__ void cp_async16(uint32_t dst, const void* src) {
    asm volatile("cp.async.cg.shared.global [%0], [%1], 16;"
                 :: "r"(dst), "l"(src) : "memory");
}
#define CP_COMMIT() asm volatile("cp.async.commit_group;" ::: "memory")
#define CP_WAIT0()  asm volatile("cp.async.wait_group 0;" ::: "memory")

__device__ __forceinline__ uint32_t pack2(__half a, __half b) {
    __half2 h = __halves2half2(a, b);
    return *(uint32_t*)&h;
}

// P = exp2(d - m) in half2 domain, returns packed fp16x2 bits
__device__ __forceinline__ uint32_t p_h2(uint32_t d_bits, __half2 m2) {
    __half2 d = *(__half2*)&d_bits;
    __half2 p = h2exp2(__hsub2(d, m2));
    return *(uint32_t*)&p;
}

// XOR-swizzled LDS.32 from [row][64-half = 128B] tile
__device__ __forceinline__ uint32_t lds32(const char* base, uint32_t row, uint32_t chunk, uint32_t cB) {
    return *(const uint32_t*)(base + row * 128 + ((chunk ^ (row & 7u)) << 4) + cB * 4);
}

// ===========================================================================
// merged conversion kernel: x -> fp16; weights -> fp16.
// grid: [0,4096) = x ; [4096, 4096+4*256) = Wq,Wk,Wv,Wo
// ===========================================================================
__global__ __launch_bounds__(256) void conv_all_kernel(
    const float* __restrict__ x,
    const float* __restrict__ Wq, const float* __restrict__ Wk,
    const float* __restrict__ Wv, const float* __restrict__ Wo)
{
    const int bid = blockIdx.x;
    const float* src;
    uint32_t* dh32;
    int idx;
    if (bid < 4096) {
        src = x; dh32 = (uint32_t*)g_xh;
        idx = bid * 256 + threadIdx.x;
    } else {
        const int w = (bid - 4096) >> 8;
        src = (w == 0) ? Wq : (w == 1) ? Wk : (w == 2) ? Wv : Wo;
        dh32 = (uint32_t*)(g_wh + (size_t)w * DD * DD);
        idx = ((bid - 4096) & 255) * 256 + threadIdx.x;
    }
    float4 f = ((const float4*)src)[idx];
    __half2 a = __floats2half2_rn(f.x, f.y);
    __half2 b = __floats2half2_rn(f.z, f.w);
    dh32[idx * 2 + 0] = *(uint32_t*)&a;
    dh32[idx * 2 + 1] = *(uint32_t*)&b;
}

// ===========================================================================
// fp16 GEMM, uniform 1-term: C = A_h @ B_h^T.
//   z=0 Q, z=1 K: A=x B=W         (result stored fp16, Q pre-scaled)
//   z=2 V^T:      A=Wv B=x        (transposed output for attention)
//   z=3 out:      A=attn B=Wo +bo (final f32 output)
// smem: 2 stages x 2 tiles x [128 rows][128B] = 64KB
// ===========================================================================

#define GEMM_SMEM 65536

__global__ __launch_bounds__(256) void hgemm_kernel(
    int mode_arg, const float* __restrict__ bo, float* __restrict__ outp)
{
    extern __shared__ char smem[];
    const uint32_t sbase = smem_u32(smem);

    const int tid  = threadIdx.x;
    const int lane = tid & 31;
    const int warp = tid >> 5;
    const int r0   = lane >> 2;
    const int cB   = lane & 3;
    const int wm   = (warp >> 1) * 32;
    const int wn   = (warp & 1) * 64;
    const int bx   = blockIdx.x;
    const int by   = blockIdx.y;
    const int z    = (mode_arg < 0) ? (int)blockIdx.z : mode_arg;

    const __half *pa_h, *pb_h;
    size_t arow0, brow0;
    if (z == 0)      { pa_h = g_xh; pb_h = g_wh;              arow0 = (size_t)by * 128; brow0 = (size_t)bx * 128; }
    else if (z == 1) { pa_h = g_xh; pb_h = g_wh + 262144;     arow0 = (size_t)by * 128; brow0 = (size_t)bx * 128; }
    else if (z == 2) { pa_h = g_wh + 2 * 262144; pb_h = g_xh; arow0 = (size_t)bx * 128; brow0 = (size_t)by * 128; }
    else             { pa_h = g_ah; pb_h = g_wh + 3 * 262144; arow0 = (size_t)by * 128; brow0 = (size_t)bx * 128; }

    const int lrow = tid >> 1;
    const int c0l  = (tid & 1) * 4;

    auto issue = [&](int stage, int k0) {
        const uint32_t sw = ((uint32_t)lrow & 7u);
        const uint32_t rowoff = (uint32_t)lrow * 128u;
        const uint32_t st = sbase + stage * 32768;
        const __half* sA = pa_h + (arow0 + lrow) * DD + k0;
        const __half* sB = pb_h + (brow0 + lrow) * DD + k0;
#pragma unroll
        for (int i = 0; i < 4; i++) {
            const uint32_t c = (uint32_t)(c0l + i);
            const uint32_t so = ((c ^ sw) << 4) + rowoff;
            cp_async16(st + so,          sA + c * 8);
            cp_async16(st + 16384 + so,  sB + c * 8);
        }
    };

    float acc[2][8][4];
#pragma unroll
    for (int mf = 0; mf < 2; mf++)
#pragma unroll
        for (int nf = 0; nf < 8; nf++)
#pragma unroll
            for (int j = 0; j < 4; j++) acc[mf][nf][j] = 0.f;

    issue(0, 0);
    CP_COMMIT();

    for (int kc = 0; kc < 8; kc++) {
        CP_WAIT0();
        __syncthreads();
        if (kc + 1 < 8) { issue((kc + 1) & 1, (kc + 1) * 64); CP_COMMIT(); }

        const char* sA = smem + (kc & 1) * 32768;
        const char* sB = sA + 16384;

#pragma unroll
        for (int ks = 0; ks < 4; ks++) {
            uint32_t ah[2][4], bh[8][2];
#pragma unroll
            for (int mf = 0; mf < 2; mf++) {
                const uint32_t ra = (uint32_t)(wm + mf * 16 + r0);
                ah[mf][0] = lds32(sA, ra,     2 * ks,     cB);
                ah[mf][1] = lds32(sA, ra + 8, 2 * ks,     cB);
                ah[mf][2] = lds32(sA, ra,     2 * ks + 1, cB);
                ah[mf][3] = lds32(sA, ra + 8, 2 * ks + 1, cB);
            }
#pragma unroll
            for (int nf = 0; nf < 8; nf++) {
                const uint32_t rb = (uint32_t)(wn + nf * 8 + r0);
                bh[nf][0] = lds32(sB, rb, 2 * ks,     cB);
                bh[nf][1] = lds32(sB, rb, 2 * ks + 1, cB);
            }
#pragma unroll
            for (int mf = 0; mf < 2; mf++)
#pragma unroll
                for (int nf = 0; nf < 8; nf++)
                    mma_f16(acc[mf][nf], ah[mf], bh[nf]);
        }
    }

    if (z == 0 || z == 1) {
        __half* outq = (z == 0) ? g_qh : g_kh;
        const float sc = (z == 0) ? (SCALE_F * LOG2E_F) : 1.f;
#pragma unroll
        for (int mf = 0; mf < 2; mf++) {
            const int tokA = by * 128 + wm + mf * 16 + r0;
#pragma unroll
            for (int nf = 0; nf < 8; nf++) {
                const int oo = bx * 128 + wn + nf * 8 + 2 * cB;
                const int h = oo >> 6, dd = oo & 63;
#pragma unroll
                for (int half_ = 0; half_ < 2; half_++) {
                    const int tok = tokA + half_ * 8;
                    const int b = tok >> 12, n = tok & (NN - 1);
                    const float v0 = acc[mf][nf][2 * half_ + 0] * sc;
                    const float v1 = acc[mf][nf][2 * half_ + 1] * sc;
                    *(uint32_t*)(outq + (((size_t)(b * HH + h) * NN) + n) * DH + dd) =
                        pack2(__float2half_rn(v0), __float2half_rn(v1));
                }
            }
        }
    } else if (z == 2) {
#pragma unroll
        for (int mf = 0; mf < 2; mf++) {
            const int frA = bx * 128 + wm + mf * 16 + r0;
#pragma unroll
            for (int nf = 0; nf < 8; nf++) {
                const int tk = by * 128 + wn + nf * 8 + 2 * cB;
                const int b = tk >> 12, n = tk & (NN - 1);
#pragma unroll
                for (int half_ = 0; half_ < 2; half_++) {
                    const int fr = frA + half_ * 8;
                    const int h = fr >> 6, dd = fr & 63;
                    const float v0 = acc[mf][nf][2 * half_ + 0];
                    const float v1 = acc[mf][nf][2 * half_ + 1];
                    *(uint32_t*)(g_vth + (((size_t)(b * HH + h) * DH) + dd) * NN + n) =
                        pack2(__float2half_rn(v0), __float2half_rn(v1));
                }
            }
        }
    } else {
#pragma unroll
        for (int mf = 0; mf < 2; mf++) {
            const int tokA = by * 128 + wm + mf * 16 + r0;
#pragma unroll
            for (int nf = 0; nf < 8; nf++) {
                const int oo = bx * 128 + wn + nf * 8 + 2 * cB;
                const float b0 = bo[oo], b1 = bo[oo + 1];
#pragma unroll
                for (int half_ = 0; half_ < 2; half_++) {
                    const int tok = tokA + half_ * 8;
                    float2 v;
                    v.x = acc[mf][nf][2 * half_ + 0] + b0;
                    v.y = acc[mf][nf][2 * half_ + 1] + b1;
                    *(float2*)(outp + (size_t)tok * DD + oo) = v;
                }
            }
        }
    }
}

// ===========================================================================
// Flash attention (core frozen since R10/R12): QK f16-acc, half2 softmax,
// guarded rescale, l via ones-mma, PV f32-acc. Epilogue: fp16 hi only.
// ===========================================================================

#define SM_TOT 32768

__global__ void __launch_bounds__(256, 2) attn_mma_kernel()
{
    extern __shared__ char smem[];
    const uint32_t sbase = smem_u32(smem);

    const int tid  = threadIdx.x;
    const int lane = tid & 31;
    const int warp = tid >> 5;
    const int bh   = blockIdx.y;
    const int q0   = blockIdx.x * 128;
    const int wrow = warp * 16;
    const int r0   = lane >> 2;
    const int cB   = lane & 3;

    const __half* khg  = g_kh  + (size_t)bh * NN * DH;
    const __half* vthg = g_vth + (size_t)bh * NN * DH;

    const int rowL = tid >> 2;
    const int fq   = tid & 3;

    {
        const char* ksrc = (const char*)(khg + (size_t)rowL * DH);
        const char* vsrc = (const char*)(vthg + (size_t)rowL * NN);
        const uint32_t kdst = sbase + rowL * 128;
        const uint32_t vdst = sbase + 16384 + rowL * 128;
        const uint32_t sw = (uint32_t)(rowL & 7);
        cp_async16(kdst + (((uint32_t)fq       ^ sw) << 4), ksrc + fq * 16);
        cp_async16(kdst + (((uint32_t)(fq + 4) ^ sw) << 4), ksrc + (fq + 4) * 16);
        cp_async16(vdst + (((uint32_t)fq       ^ sw) << 4), vsrc + fq * 16);
        cp_async16(vdst + (((uint32_t)(fq + 4) ^ sw) << 4), vsrc + (fq + 4) * 16);
        CP_COMMIT();
    }

    uint32_t qa[4][4];
    {
        const __half* qg = g_qh + ((size_t)bh * NN + q0 + wrow + r0) * DH;
#pragma unroll
        for (int s4 = 0; s4 < 4; s4++) {
            qa[s4][0] = *(const uint32_t*)(qg + s4 * 16 + 2 * cB);
            qa[s4][1] = *(const uint32_t*)(qg + 8 * DH + s4 * 16 + 2 * cB);
            qa[s4][2] = *(const uint32_t*)(qg + s4 * 16 + 2 * cB + 8);
            qa[s4][3] = *(const uint32_t*)(qg + 8 * DH + s4 * 16 + 2 * cB + 8);
        }
    }

    float o[8][4];
#pragma unroll
    for (int n = 0; n < 8; n++)
#pragma unroll
        for (int j = 0; j < 4; j++) o[n][j] = 0.f;
    float m0 = -1e30f, m1 = -1e30f, l0 = 0.f, l1 = 0.f;

    const uint32_t ones[2] = {0x3C003C00u, 0x3C003C00u};

    for (int t = 0; t < NN / 64; t++) {
        CP_WAIT0();
        __syncthreads();

        if (t + 1 < NN / 64) {
            const int buf = (t + 1) & 1;
            const char* ksrc = (const char*)(khg + ((size_t)(t + 1) * 64 + rowL) * DH);
            const char* vsrc = (const char*)(vthg + (size_t)rowL * NN + (t + 1) * 64);
            const uint32_t kdst = sbase + buf * 8192 + rowL * 128;
            const uint32_t vdst = sbase + 16384 + buf * 8192 + rowL * 128;
            const uint32_t sw = (uint32_t)(rowL & 7);
            cp_async16(kdst + (((uint32_t)fq       ^ sw) << 4), ksrc + fq * 16);
            cp_async16(kdst + (((uint32_t)(fq + 4) ^ sw) << 4), ksrc + (fq + 4) * 16);
            cp_async16(vdst + (((uint32_t)fq       ^ sw) << 4), vsrc + fq * 16);
            cp_async16(vdst + (((uint32_t)(fq + 4) ^ sw) << 4), vsrc + (fq + 4) * 16);
            CP_COMMIT();
        }

        const char* sK = smem + (t & 1) * 8192;
        const char* sV = smem + 16384 + (t & 1) * 8192;

        // ---- S = Q @ K^T, f16 accumulator ----
        uint32_t sc[8][2];
#pragma unroll
        for (int n = 0; n < 8; n++) { sc[n][0] = 0u; sc[n][1] = 0u; }

#pragma unroll
        for (int s4 = 0; s4 < 4; s4++) {
#pragma unroll
            for (int n = 0; n < 8; n++) {
                const uint32_t row = (uint32_t)(n * 8 + r0);
                uint32_t b[2];
                b[0] = lds32(sK, row, 2 * s4,     (uint32_t)cB);
                b[1] = lds32(sK, row, 2 * s4 + 1, (uint32_t)cB);
                mma_f16h(sc[n], qa[s4], b);
            }
        }

        // ---- online softmax, half2 domain ----
        __half2 hx0 = *(__half2*)&sc[0][0];
        __half2 hx1 = *(__half2*)&sc[0][1];
#pragma unroll
        for (int n = 1; n < 8; n++) {
            hx0 = __hmax2(hx0, *(__half2*)&sc[n][0]);
            hx1 = __hmax2(hx1, *(__half2*)&sc[n][1]);
        }
        float mx0 = fmaxf(__low2float(hx0), __high2float(hx0));
        float mx1 = fmaxf(__low2float(hx1), __high2float(hx1));
        mx0 = fmaxf(mx0, __shfl_xor_sync(0xffffffffu, mx0, 1));
        mx0 = fmaxf(mx0, __shfl_xor_sync(0xffffffffu, mx0, 2));
        mx1 = fmaxf(mx1, __shfl_xor_sync(0xffffffffu, mx1, 1));
        mx1 = fmaxf(mx1, __shfl_xor_sync(0xffffffffu, mx1, 2));

        if (mx0 > m0) {
            const float a0 = ex2f(m0 - mx0);
            l0 *= a0;
#pragma unroll
            for (int n = 0; n < 8; n++) { o[n][0] *= a0; o[n][1] *= a0; }
            m0 = mx0;
        }
        if (mx1 > m1) {
            const float a1 = ex2f(m1 - mx1);
            l1 *= a1;
#pragma unroll
            for (int n = 0; n < 8; n++) { o[n][2] *= a1; o[n][3] *= a1; }
            m1 = mx1;
        }

        const __half2 m0h2 = __floats2half2_rn(m0, m0);
        const __half2 m1h2 = __floats2half2_rn(m1, m1);

        // ---- P = exp2(S - m); O += P @ V; l via ones-mma ----
        float ls[4] = {0.f, 0.f, 0.f, 0.f};
#pragma unroll
        for (int s4 = 0; s4 < 4; s4++) {
            uint32_t pa[4];
            pa[0] = p_h2(sc[2 * s4][0],     m0h2);
            pa[1] = p_h2(sc[2 * s4][1],     m1h2);
            pa[2] = p_h2(sc[2 * s4 + 1][0], m0h2);
            pa[3] = p_h2(sc[2 * s4 + 1][1], m1h2);
            mma_f16(ls, pa, ones);
#pragma unroll
            for (int n = 0; n < 8; n++) {
                const uint32_t row = (uint32_t)(n * 8 + r0);
                uint32_t b[2];
                b[0] = lds32(sV, row, 2 * s4,     (uint32_t)cB);
                b[1] = lds32(sV, row, 2 * s4 + 1, (uint32_t)cB);
                mma_f16(o[n], pa, b);
            }
        }
        l0 += ls[0];
        l1 += ls[2];
    }

    // ---- epilogue: normalize, store fp16 (out-proj is 1-term now) ----
    const float inv0 = 1.f / l0;
    const float inv1 = 1.f / l1;
    const int b = bh >> 3, h = bh & 7;
    const int row0 = q0 + wrow + r0;
    const size_t off0 = ((size_t)(b * NN + row0)) * DD + h * DH;
    const size_t off1 = off0 + (size_t)8 * DD;
#pragma unroll
    for (int n = 0; n < 8; n++) {
        const int col = n * 8 + 2 * cB;
        *(uint32_t*)(g_ah + off0 + col) =
            pack2(__float2half_rn(o[n][0] * inv0), __float2half_rn(o[n][1] * inv0));
        *(uint32_t*)(g_ah + off1 + col) =
            pack2(__float2half_rn(o[n][2] * inv1), __float2half_rn(o[n][3] * inv1));
    }
}

// ===========================================================================

extern "C" void kernel_launch(void* const* d_in, const int* in_sizes, int n_in,
                              void* d_out, int out_size)
{
    (void)in_sizes; (void)n_in; (void)out_size;
    const float* x  = (const float*)d_in[0];
    const float* Wq = (const float*)d_in[1];
    const float* Wk = (const float*)d_in[2];
    const float* Wv = (const float*)d_in[3];
    const float* Wo = (const float*)d_in[4];
    const float* bo = (const float*)d_in[5];
    float* out = (float*)d_out;

    cudaFuncSetAttribute(hgemm_kernel,
                         cudaFuncAttributeMaxDynamicSharedMemorySize, GEMM_SMEM);
    cudaFuncSetAttribute(attn_mma_kernel,
                         cudaFuncAttributeMaxDynamicSharedMemorySize, SM_TOT);

    // merged conversions (x + 4 weights) in one launch
    conv_all_kernel<<<4096 + 4 * 256, 256>>>(x, Wq, Wk, Wv, Wo);

    // QKV projections (1-term fp16)
    hgemm_kernel<<<dim3(4, 64, 3), 256, GEMM_SMEM>>>(-1, nullptr, nullptr);
    // Flash attention
    attn_mma_kernel<<<dim3(NN / 128, BB * HH), 256, SM_TOT>>>();
    // Output projection + bias (1-term fp16, f32 accum + f32 bias)
    hgemm_kernel<<<dim3(4, 64, 1), 256, GEMM_SMEM>>>(3, bo, out);
}